// round 7
// baseline (speedup 1.0000x reference)
#include <cuda_runtime.h>
#include <cuda_bf16.h>
#include <stdint.h>

// Shapes: bs=16384, din=512, mid=1024, out=512, K=2, D1=2, D2=4
//
// Two GEMMs via 2-digit int8 decomposition on mma.sync.m16n8k32.s8:
//   v ~ (d1 + d2/256)*s,  d1,d2 int8. Per k32: D1=d1a*d1b, D2=d1a*d2b+d2a*d1b
//   (int32 exact), fold: facc += s * (D1 + D2/256).   Drop d2a*d2b (~2^-14).
//   A1 (bs x 1024)  = interleave(q1_0, x)
//   h1 (bs x 1024)  = bn1(relu(A1 @ w1^T + b1))         [quantized online, bound 16]
//   A2 (bs x 3072)  = [q2_0 | h1 | A1]   (K-reordered; per-segment scales)
//   WC (512 x 3072) = [w2 even | w2 odd | w_skip]
//   out (bs x 512)  = bn2(relu(A2 @ WC^T + b2 + b_skip))

#define BSZ   16384
#define KD1   1024
#define KD2   3072
#define NMID  1024
#define NOUT  512
#define EPSBN 1e-5f

#define BM 128
#define BN 128
#define BK 128                          // int8 elems -> 128B rows
#define STAGES 3
#define TILE_BYTES  (128 * 128)         // 16 KB per tile plane
#define STAGE_BYTES (4 * TILE_BYTES)    // Ad1 | Ad2 | Bd1 | Bd2 = 64 KB
#define SMEM_BYTES  (STAGES * STAGE_BYTES)   // 192 KB

#define SH_BOUND 16.0f                  // fixed h1 quantization bound

// ---------------------------------------------------------------------------
// Scratch (static device arrays: allocation-free)
// ---------------------------------------------------------------------------
static __device__ float g_max[4];       // 0:A1(q1,x) 1:q2 2:w1 3:WC(w2,wsk)
static __device__ int8_t g_A1d1[(size_t)BSZ*KD1], g_A1d2[(size_t)BSZ*KD1];
static __device__ int8_t g_A2d1[(size_t)BSZ*KD2], g_A2d2[(size_t)BSZ*KD2];
static __device__ int8_t g_W1d1[(size_t)NMID*KD1], g_W1d2[(size_t)NMID*KD1];
static __device__ int8_t g_WCd1[(size_t)NOUT*KD2], g_WCd2[(size_t)NOUT*KD2];

// ---------------------------------------------------------------------------
// PTX helpers (plain sm_80-era PTX)
// ---------------------------------------------------------------------------
__device__ __forceinline__ uint32_t smem_u32(const void* p) {
    uint32_t a;
    asm("{ .reg .u64 t; cvta.to.shared.u64 t, %1; cvt.u32.u64 %0, t; }" : "=r"(a) : "l"(p));
    return a;
}
__device__ __forceinline__ void cp16(uint32_t s, const void* g) {
    asm volatile("cp.async.cg.shared.global [%0], [%1], 16;" :: "r"(s), "l"(g));
}
__device__ __forceinline__ void cp_commit() {
    asm volatile("cp.async.commit_group;" ::: "memory");
}
__device__ __forceinline__ void cp_wait1() {
    asm volatile("cp.async.wait_group 1;" ::: "memory");
}
__device__ __forceinline__ void ldm4(uint32_t& r0, uint32_t& r1, uint32_t& r2, uint32_t& r3,
                                     uint32_t addr) {
    asm volatile("ldmatrix.sync.aligned.m8n8.x4.shared.b16 {%0,%1,%2,%3}, [%4];"
                 : "=r"(r0), "=r"(r1), "=r"(r2), "=r"(r3) : "r"(addr));
}
__device__ __forceinline__ void ldm2(uint32_t& r0, uint32_t& r1, uint32_t addr) {
    asm volatile("ldmatrix.sync.aligned.m8n8.x2.shared.b16 {%0,%1}, [%2];"
                 : "=r"(r0), "=r"(r1) : "r"(addr));
}
// D = a*b (fresh, c = 0)
__device__ __forceinline__ void mma_s8_z(int32_t* d, const uint32_t* a, const uint32_t* b) {
    asm volatile("mma.sync.aligned.m16n8k32.row.col.s32.s8.s8.s32 "
                 "{%0,%1,%2,%3}, {%4,%5,%6,%7}, {%8,%9}, {%10,%10,%10,%10};"
                 : "=r"(d[0]), "=r"(d[1]), "=r"(d[2]), "=r"(d[3])
                 : "r"(a[0]), "r"(a[1]), "r"(a[2]), "r"(a[3]),
                   "r"(b[0]), "r"(b[1]), "r"(0));
}
// D += a*b
__device__ __forceinline__ void mma_s8_a(int32_t* d, const uint32_t* a, const uint32_t* b) {
    asm volatile("mma.sync.aligned.m16n8k32.row.col.s32.s8.s8.s32 "
                 "{%0,%1,%2,%3}, {%4,%5,%6,%7}, {%8,%9}, {%0,%1,%2,%3};"
                 : "+r"(d[0]), "+r"(d[1]), "+r"(d[2]), "+r"(d[3])
                 : "r"(a[0]), "r"(a[1]), "r"(a[2]), "r"(a[3]),
                   "r"(b[0]), "r"(b[1]));
}
__device__ __forceinline__ uint32_t sw128(uint32_t o) { return o ^ ((o >> 3) & 0x70); }

// 2-digit int8 quantization: v ~ (d1 + d2/256)*(M/127), invs = 127/M
__device__ __forceinline__ void iq2(float v, float invs, int8_t& d1, int8_t& d2) {
    float t = fminf(fmaxf(v * invs, -127.f), 127.f);
    float r1 = rintf(t);
    d1 = (int8_t)(int)r1;
    float r2 = fminf(fmaxf(rintf((t - r1) * 256.f), -127.f), 127.f);
    d2 = (int8_t)(int)r2;
}
__device__ __forceinline__ int16_t pk2(int8_t a, int8_t b) {
    return (int16_t)(uint16_t)(((uint16_t)(uint8_t)a) | ((uint16_t)(uint8_t)b << 8));
}

// ---------------------------------------------------------------------------
// Scale kernels
// ---------------------------------------------------------------------------
__global__ void kzero() {
    if (threadIdx.x < 4) g_max[threadIdx.x] = 0.0f;
}

// regions (4096 elems per block, 256 thr x 16 elems):
//   q1:[0,2048) x:[2048,4096) q2:[4096,8192) w1:[8192,8448) w2:[8448,8704) wsk:[8704,8832)
__global__ void kmax(const float* __restrict__ q1, const float* __restrict__ x,
                     const float* __restrict__ q2, const float* __restrict__ w1,
                     const float* __restrict__ w2, const float* __restrict__ wsk) {
    __shared__ float sred[256];
    int b = blockIdx.x;
    const float* src;
    int tgt, rb;
    if      (b < 2048) { src = q1;  tgt = 0; rb = b; }
    else if (b < 4096) { src = x;   tgt = 0; rb = b - 2048; }
    else if (b < 8192) { src = q2;  tgt = 1; rb = b - 4096; }
    else if (b < 8448) { src = w1;  tgt = 2; rb = b - 8192; }
    else if (b < 8704) { src = w2;  tgt = 3; rb = b - 8448; }
    else               { src = wsk; tgt = 3; rb = b - 8704; }
    size_t base = (size_t)rb * 4096 + threadIdx.x;
    float m = 0.0f;
    #pragma unroll
    for (int k = 0; k < 16; k++) m = fmaxf(m, fabsf(src[base + (size_t)k * 256]));
    sred[threadIdx.x] = m;
    __syncthreads();
    for (int s = 128; s > 0; s >>= 1) {
        if (threadIdx.x < s) sred[threadIdx.x] = fmaxf(sred[threadIdx.x], sred[threadIdx.x + s]);
        __syncthreads();
    }
    if (threadIdx.x == 0)
        atomicMax(reinterpret_cast<unsigned*>(&g_max[tgt]), __float_as_uint(sred[0]));
}

// ---------------------------------------------------------------------------
// Quantize/pack kernel (range-partitioned)
// ---------------------------------------------------------------------------
#define NP0 (BSZ * 512)           // a1 pairs (q1, x)
#define NP1 (BSZ * 512)           // q2 float2s
#define NP2 (NMID * KD1 / 2)      // w1 float2s
#define NP3 (NOUT * KD2)          // wcat singles
#define NPTOT (NP0 + NP1 + NP2 + NP3)

__global__ void kquant(const float* __restrict__ q1, const float* __restrict__ x,
                       const float* __restrict__ q2, const float* __restrict__ w1,
                       const float* __restrict__ w2, const float* __restrict__ wsk) {
    int i = blockIdx.x * blockDim.x + threadIdx.x;
    if (i < NP0) {
        float invs = 127.f / fmaxf(g_max[0], 1e-20f);
        int m = i >> 9, c = i & 511;
        int8_t a1, a2, b1, b2;
        iq2(q1[i], invs, a1, a2);
        iq2(x[i],  invs, b1, b2);
        int16_t p1 = pk2(a1, b1), p2 = pk2(a2, b2);
        size_t o1 = (size_t)m * KD1 + 2 * c;
        *reinterpret_cast<int16_t*>(&g_A1d1[o1]) = p1;
        *reinterpret_cast<int16_t*>(&g_A1d2[o1]) = p2;
        size_t o2 = (size_t)m * KD2 + 2048 + 2 * c;     // A1 copy region of A2
        *reinterpret_cast<int16_t*>(&g_A2d1[o2]) = p1;
        *reinterpret_cast<int16_t*>(&g_A2d2[o2]) = p2;
    } else if (i < NP0 + NP1) {
        float invs = 127.f / fmaxf(g_max[1], 1e-20f);
        int j = i - NP0;
        int m = j >> 9, c2 = (j & 511) * 2;
        float2 v = reinterpret_cast<const float2*>(q2)[j];
        int8_t a1, a2, b1, b2;
        iq2(v.x, invs, a1, a2);
        iq2(v.y, invs, b1, b2);
        size_t o = (size_t)m * KD2 + c2;
        *reinterpret_cast<int16_t*>(&g_A2d1[o]) = pk2(a1, b1);
        *reinterpret_cast<int16_t*>(&g_A2d2[o]) = pk2(a2, b2);
    } else if (i < NP0 + NP1 + NP2) {
        float invs = 127.f / fmaxf(g_max[2], 1e-20f);
        int j = i - NP0 - NP1;
        float2 v = reinterpret_cast<const float2*>(w1)[j];
        int8_t a1, a2, b1, b2;
        iq2(v.x, invs, a1, a2);
        iq2(v.y, invs, b1, b2);
        *reinterpret_cast<int16_t*>(&g_W1d1[2*j]) = pk2(a1, b1);
        *reinterpret_cast<int16_t*>(&g_W1d2[2*j]) = pk2(a2, b2);
    } else if (i < NPTOT) {
        float invs = 127.f / fmaxf(g_max[3], 1e-20f);
        int j = i - NP0 - NP1 - NP2;
        int n = j / KD2, c = j - n * KD2;
        float v;
        if (c < 1024)       v = w2[(size_t)n * 2048 + 2 * c];               // pairs q2
        else if (c < 2048)  v = w2[(size_t)n * 2048 + 2 * (c - 1024) + 1];  // pairs h1
        else                v = wsk[(size_t)n * 1024 + (c - 2048)];         // skip
        int8_t d1, d2;
        iq2(v, invs, d1, d2);
        g_WCd1[j] = d1; g_WCd2[j] = d2;
    }
}

// ---------------------------------------------------------------------------
// int8 2-digit GEMM: 128x128 CTA, BK=128, 3-stage cp.async pipeline.
// 8 warps: warp_m = wid&1 (64 rows), warp_n = wid>>1 (32 cols).
// MODE 0: A1 @ W1^T -> h1 quantized (2 digits, bound 16) into A2 cols 1024..2047
// MODE 1: A2 @ WC^T (3 K-segments, per-segment scales) -> fp32 out
// ---------------------------------------------------------------------------
template<int MODE>
__global__ void __launch_bounds__(256) gemm_kernel(
    const float* __restrict__ pb0, const float* __restrict__ pb1,
    const float* __restrict__ psc, const float* __restrict__ pbi,
    const float* __restrict__ pmu, const float* __restrict__ pva,
    float* __restrict__ outp)
{
    extern __shared__ __align__(1024) char smem[];
    const uint32_t sb = smem_u32(smem);
    const int tid = threadIdx.x;
    const int wid = tid >> 5, lane = tid & 31;
    const int warp_m = wid & 1;      // 64-row slices
    const int warp_n = wid >> 1;     // 32-col slices
    const int blockRow = blockIdx.y * BM, blockCol = blockIdx.x * BN;

    constexpr int KDIM = (MODE == 0) ? KD1 : KD2;
    constexpr int KC   = KDIM / BK;  // 8 or 24

    const int8_t* Ad1 = (MODE == 0) ? g_A1d1 : g_A2d1;
    const int8_t* Ad2 = (MODE == 0) ? g_A1d2 : g_A2d2;
    const int8_t* Bd1 = (MODE == 0) ? g_W1d1 : g_WCd1;
    const int8_t* Bd2 = (MODE == 0) ? g_W1d2 : g_WCd2;

    // fold scales
    float sc_c, scs0, scs1, scs2;
    if (MODE == 0) {
        sc_c = g_max[0] * g_max[2] * (1.f / (127.f * 127.f));
        scs0 = scs1 = scs2 = sc_c;
    } else {
        float sW = g_max[3] * (1.f / 127.f);
        scs0 = g_max[1] * (1.f / 127.f) * sW;
        scs1 = (SH_BOUND / 127.f) * sW;
        scs2 = g_max[0] * (1.f / 127.f) * sW;
        sc_c = scs0;
    }

    // cp.async: thread t -> row t/2, 64B half (t&1), 4 cp16 per plane
    const int ldrow = tid >> 1, half = tid & 1;
    const int8_t* pA1 = Ad1 + (size_t)(blockRow + ldrow) * KDIM + half * 64;
    const int8_t* pA2 = Ad2 + (size_t)(blockRow + ldrow) * KDIM + half * 64;
    const int8_t* pB1 = Bd1 + (size_t)(blockCol + ldrow) * KDIM + half * 64;
    const int8_t* pB2 = Bd2 + (size_t)(blockCol + ldrow) * KDIM + half * 64;
    uint32_t swoff[4];
    #pragma unroll
    for (int j = 0; j < 4; j++)
        swoff[j] = sw128((uint32_t)ldrow * 128u + (uint32_t)(half * 64 + j * 16));

    auto load_chunk = [&](int i) {
        uint32_t bs_ = sb + (uint32_t)(i % STAGES) * STAGE_BYTES;
        const int8_t* a1 = pA1 + i * BK;
        const int8_t* a2 = pA2 + i * BK;
        const int8_t* b1 = pB1 + i * BK;
        const int8_t* b2 = pB2 + i * BK;
        #pragma unroll
        for (int j = 0; j < 4; j++) cp16(bs_ +                swoff[j], a1 + j * 16);
        #pragma unroll
        for (int j = 0; j < 4; j++) cp16(bs_ + 1*TILE_BYTES + swoff[j], a2 + j * 16);
        #pragma unroll
        for (int j = 0; j < 4; j++) cp16(bs_ + 2*TILE_BYTES + swoff[j], b1 + j * 16);
        #pragma unroll
        for (int j = 0; j < 4; j++) cp16(bs_ + 3*TILE_BYTES + swoff[j], b2 + j * 16);
    };

    float facc[4][4][4] = {};   // [mtile16][ntile8][frag]

    // ldmatrix per-thread address bases
    const uint32_t a_base = (uint32_t)(warp_m * 64 + (lane & 7) + ((lane >> 3) & 1) * 8) * 128u
                          + (uint32_t)(lane >> 4) * 16u;
    const uint32_t b_base = (uint32_t)(warp_n * 32 + (lane & 7)) * 128u
                          + (uint32_t)((lane >> 3) & 1) * 16u;

    load_chunk(0); cp_commit();
    load_chunk(1); cp_commit();

    for (int i = 0; i < KC; i++) {
        cp_wait1();
        __syncthreads();
        if (i + 2 < KC) load_chunk(i + 2);
        cp_commit();

        float sc;
        if (MODE == 0) sc = sc_c;
        else { int seg = i >> 3; sc = (seg == 0) ? scs0 : ((seg == 1) ? scs1 : scs2); }

        uint32_t st  = sb + (uint32_t)(i % STAGES) * STAGE_BYTES;
        uint32_t sA1 = st, sA2 = st + 1*TILE_BYTES, sB1 = st + 2*TILE_BYTES, sB2 = st + 3*TILE_BYTES;

        #pragma unroll
        for (int s = 0; s < 4; s++) {          // k32 steps within chunk
            uint32_t a1[4][4], a2[4][4], b1[4][2], b2[4][2];
            #pragma unroll
            for (int it = 0; it < 4; it++) {
                uint32_t ro = sw128(a_base + (uint32_t)it * 2048u + (uint32_t)s * 32u);
                ldm4(a1[it][0], a1[it][1], a1[it][2], a1[it][3], sA1 + ro);
                ldm4(a2[it][0], a2[it][1], a2[it][2], a2[it][3], sA2 + ro);
            }
            #pragma unroll
            for (int jn = 0; jn < 4; jn++) {
                uint32_t ro = sw128(b_base + (uint32_t)jn * 1024u + (uint32_t)s * 32u);
                ldm2(b1[jn][0], b1[jn][1], sB1 + ro);
                ldm2(b2[jn][0], b2[jn][1], sB2 + ro);
            }
            #pragma unroll
            for (int it = 0; it < 4; it++)
                #pragma unroll
                for (int jn = 0; jn < 4; jn++) {
                    int32_t D1[4], D2[4];
                    mma_s8_z(D1, a1[it], b1[jn]);     // d1*d1
                    mma_s8_z(D2, a1[it], b2[jn]);     // d1*d2
                    mma_s8_a(D2, a2[it], b1[jn]);     // + d2*d1
                    #pragma unroll
                    for (int f = 0; f < 4; f++) {
                        float t = fmaf((float)D2[f], 0.00390625f, (float)D1[f]);
                        facc[it][jn][f] = fmaf(sc, t, facc[it][jn][f]);
                    }
                }
        }
    }

    // ------------------- epilogue -------------------
    __syncthreads();
    float* sp = (float*)smem;
    if (tid < BN) {
        int n = blockCol + tid;
        float se = psc[n] * rsqrtf(pva[n] + EPSBN);
        sp[tid]           = se;
        sp[BN + tid]      = pbi[n] - pmu[n] * se;
        sp[2 * BN + tid]  = (MODE == 0) ? pb0[n] : (pb0[n] + pb1[n]);
    }
    __syncthreads();

    const int groupID = lane >> 2;
    const int colPair = (lane & 3) * 2;
    const float invs_h = 127.f / SH_BOUND;

    #pragma unroll
    for (int it = 0; it < 4; it++) {
        #pragma unroll
        for (int jn = 0; jn < 4; jn++) {
            int lc = warp_n * 32 + jn * 8 + colPair;
            float se0 = sp[lc],      se1 = sp[lc + 1];
            float of0 = sp[BN+lc],   of1 = sp[BN+lc+1];
            float bb0 = sp[2*BN+lc], bb1 = sp[2*BN+lc+1];
            #pragma unroll
            for (int rr = 0; rr < 2; rr++) {
                int m = blockRow + warp_m * 64 + it * 16 + groupID + rr * 8;
                float v0 = fmaf(fmaxf(facc[it][jn][2*rr]   + bb0, 0.0f), se0, of0);
                float v1 = fmaf(fmaxf(facc[it][jn][2*rr+1] + bb1, 0.0f), se1, of1);
                if (MODE == 0) {
                    int8_t x1, x2, y1, y2;
                    iq2(v0, invs_h, x1, x2);
                    iq2(v1, invs_h, y1, y2);
                    size_t o = (size_t)m * KD2 + 1024 + blockCol + lc;
                    *reinterpret_cast<int16_t*>(&g_A2d1[o]) = pk2(x1, y1);
                    *reinterpret_cast<int16_t*>(&g_A2d2[o]) = pk2(x2, y2);
                } else {
                    size_t o = (size_t)m * NOUT + blockCol + lc;
                    *reinterpret_cast<float2*>(&outp[o]) = make_float2(v0, v1);
                }
            }
        }
    }
}

// ---------------------------------------------------------------------------
// Launch (no static guards — identical work on every call)
// ---------------------------------------------------------------------------
extern "C" void kernel_launch(void* const* d_in, const int* in_sizes, int n_in,
                              void* d_out, int out_size) {
    const float* x    = (const float*)d_in[0];
    const float* q1   = (const float*)d_in[1];   // (2, bs, 512, 1): slice 0
    const float* q2   = (const float*)d_in[2];   // (4, bs, 1024,1): slice 0
    const float* w1   = (const float*)d_in[3];
    const float* b1   = (const float*)d_in[4];
    const float* w2   = (const float*)d_in[5];
    const float* b2   = (const float*)d_in[6];
    const float* wsk  = (const float*)d_in[7];
    const float* bsk  = (const float*)d_in[8];
    const float* s1   = (const float*)d_in[9];
    const float* bi1  = (const float*)d_in[10];
    const float* mu1  = (const float*)d_in[11];
    const float* va1  = (const float*)d_in[12];
    const float* s2   = (const float*)d_in[13];
    const float* bi2  = (const float*)d_in[14];
    const float* mu2  = (const float*)d_in[15];
    const float* va2  = (const float*)d_in[16];
    float* out = (float*)d_out;
    (void)in_sizes; (void)n_in; (void)out_size;

    cudaFuncSetAttribute(gemm_kernel<0>, cudaFuncAttributeMaxDynamicSharedMemorySize, SMEM_BYTES);
    cudaFuncSetAttribute(gemm_kernel<1>, cudaFuncAttributeMaxDynamicSharedMemorySize, SMEM_BYTES);

    kzero<<<1, 32>>>();
    kmax<<<8832, 256>>>(q1, x, q2, w1, w2, wsk);
    kquant<<<(NPTOT + 255) / 256, 256>>>(q1, x, q2, w1, w2, wsk);

    dim3 g1(NMID / BN, BSZ / BM);   // (8, 128)
    gemm_kernel<0><<<g1, 256, SMEM_BYTES>>>(b1, nullptr, s1, bi1, mu1, va1, nullptr);

    dim3 g2(NOUT / BN, BSZ / BM);   // (4, 128)
    gemm_kernel<1><<<g2, 256, SMEM_BYTES>>>(b2, bsk, s2, bi2, mu2, va2, out);
}

// round 9
// speedup vs baseline: 2.8895x; 2.8895x over previous
#include <cuda_runtime.h>
#include <cuda_fp16.h>
#include <stdint.h>

// Shapes: bs=16384, din=512, mid=1024, out=512, K=2, D1=2, D2=4
//
// Two fp16 split-precision GEMMs via mma.sync (plain PTX under compute_103):
//   A1 (bs x 1024)  = interleave(q1_0, x)          [A split: Ah + Al fp16]
//   h1 (bs x 1024)  = bn1(relu(A1 @ w1^T + b1))    [stored as fp16 hi/lo]
//   A2 (bs x 3072)  = [q2_0 | h1 | A1]             (K-reordered)
//   WC (512 x 3072) = [w2 even | w2 odd | w_skip]  [single fp16 plane]
//   out (bs x 512)  = bn2(relu(A2 @ WC^T + b2 + b_skip))
// Per k16: acc += Ah*Bh + Al*Bh  (2 MMAs; B fp16-rounding error ~2^-11
// dominates -> rel_err ~3-5e-4, within the 1e-3 gate).

#define BSZ   16384
#define KD1   1024
#define KD2   3072
#define NMID  1024
#define NOUT  512
#define EPSBN 1e-5f

#define BM 128
#define BN 128
#define BK 64                           // fp16 elems -> 128B rows
#define STAGES 4
#define TILE_BYTES  (128 * 128)         // 16 KB per plane (128 rows x 128 B)
#define STAGE_BYTES (3 * TILE_BYTES)    // Ah | Al | Bh = 48 KB
#define SMEM_BYTES  (STAGES * STAGE_BYTES)   // 192 KB

// ---------------------------------------------------------------------------
// Scratch (static device arrays: allocation-free)
// ---------------------------------------------------------------------------
static __device__ __half g_A1h[(size_t)BSZ*KD1];
static __device__ __half g_A1l[(size_t)BSZ*KD1];
static __device__ __half g_A2h[(size_t)BSZ*KD2];
static __device__ __half g_A2l[(size_t)BSZ*KD2];
static __device__ __half g_W1 [(size_t)NMID*KD1];
static __device__ __half g_WC [(size_t)NOUT*KD2];

// ---------------------------------------------------------------------------
// PTX helpers (plain sm_80-era PTX)
// ---------------------------------------------------------------------------
__device__ __forceinline__ uint32_t smem_u32(const void* p) {
    uint32_t a;
    asm("{ .reg .u64 t; cvta.to.shared.u64 t, %1; cvt.u32.u64 %0, t; }" : "=r"(a) : "l"(p));
    return a;
}
__device__ __forceinline__ void cp16(uint32_t s, const void* g) {
    asm volatile("cp.async.cg.shared.global [%0], [%1], 16;" :: "r"(s), "l"(g));
}
__device__ __forceinline__ void cp_commit() {
    asm volatile("cp.async.commit_group;" ::: "memory");
}
__device__ __forceinline__ void cp_wait2() {
    asm volatile("cp.async.wait_group 2;" ::: "memory");
}
__device__ __forceinline__ void ldm4(uint32_t& r0, uint32_t& r1, uint32_t& r2, uint32_t& r3,
                                     uint32_t addr) {
    asm volatile("ldmatrix.sync.aligned.m8n8.x4.shared.b16 {%0,%1,%2,%3}, [%4];"
                 : "=r"(r0), "=r"(r1), "=r"(r2), "=r"(r3) : "r"(addr));
}
__device__ __forceinline__ void mma16816(float* c, const uint32_t* a, const uint32_t* b) {
    asm volatile("mma.sync.aligned.m16n8k16.row.col.f32.f16.f16.f32 "
                 "{%0,%1,%2,%3}, {%4,%5,%6,%7}, {%8,%9}, {%0,%1,%2,%3};"
                 : "+f"(c[0]), "+f"(c[1]), "+f"(c[2]), "+f"(c[3])
                 : "r"(a[0]), "r"(a[1]), "r"(a[2]), "r"(a[3]), "r"(b[0]), "r"(b[1]));
}
__device__ __forceinline__ uint32_t sw128(uint32_t o) { return o ^ ((o >> 3) & 0x70); }

__device__ __forceinline__ void hsplit(float v, __half& h, __half& l) {
    h = __float2half_rn(v);
    l = __float2half_rn(v - __half2float(h));
}

// ---------------------------------------------------------------------------
// Single merged pack kernel, range-partitioned
// ---------------------------------------------------------------------------
#define NP0 (BSZ * 512)           // a1 pairs (q1, x)
#define NP1 (BSZ * 512)           // q2 float2s
#define NP2 (NMID * KD1 / 2)      // w1 float2s
#define NP3 (NOUT * KD2)          // wcat singles
#define NPTOT (NP0 + NP1 + NP2 + NP3)

__global__ void pack_all(const float* __restrict__ q1, const float* __restrict__ x,
                         const float* __restrict__ q2, const float* __restrict__ w1,
                         const float* __restrict__ w2, const float* __restrict__ wsk) {
    int i = blockIdx.x * blockDim.x + threadIdx.x;
    if (i < NP0) {
        // A1[m,2c]=q1_0[m,c], A1[m,2c+1]=x[m,c]; also copy to A2 cols 2048+
        int m = i >> 9, c = i & 511;
        __half h0, l0, h1, l1;
        hsplit(q1[i], h0, l0);
        hsplit(x[i],  h1, l1);
        __half2 hp = __halves2half2(h0, h1);
        __half2 lp = __halves2half2(l0, l1);
        size_t o1 = (size_t)m * KD1 + 2 * c;
        *reinterpret_cast<__half2*>(&g_A1h[o1]) = hp;
        *reinterpret_cast<__half2*>(&g_A1l[o1]) = lp;
        size_t o2 = (size_t)m * KD2 + 2048 + 2 * c;
        *reinterpret_cast<__half2*>(&g_A2h[o2]) = hp;
        *reinterpret_cast<__half2*>(&g_A2l[o2]) = lp;
    } else if (i < NP0 + NP1) {
        int j = i - NP0;
        int m = j >> 9, c2 = (j & 511) * 2;
        float2 v = reinterpret_cast<const float2*>(q2)[j];
        __half h0, l0, h1, l1;
        hsplit(v.x, h0, l0);
        hsplit(v.y, h1, l1);
        size_t o = (size_t)m * KD2 + c2;
        *reinterpret_cast<__half2*>(&g_A2h[o]) = __halves2half2(h0, h1);
        *reinterpret_cast<__half2*>(&g_A2l[o]) = __halves2half2(l0, l1);
    } else if (i < NP0 + NP1 + NP2) {
        int j = i - NP0 - NP1;
        float2 v = reinterpret_cast<const float2*>(w1)[j];
        *reinterpret_cast<__half2*>(&g_W1[2*j]) =
            __halves2half2(__float2half_rn(v.x), __float2half_rn(v.y));
    } else if (i < NPTOT) {
        int j = i - NP0 - NP1 - NP2;
        int n = j / KD2, c = j - n * KD2;
        float v;
        if (c < 1024)       v = w2[(size_t)n * 2048 + 2 * c];               // pairs q2
        else if (c < 2048)  v = w2[(size_t)n * 2048 + 2 * (c - 1024) + 1];  // pairs h1
        else                v = wsk[(size_t)n * 1024 + (c - 2048)];         // skip
        g_WC[j] = __float2half_rn(v);
    }
}

// ---------------------------------------------------------------------------
// Fused 2-term mma.sync GEMM: 128x128 CTA, BK=64, 4-stage cp.async pipeline.
// 8 warps: warp_m = wid&1 (64 rows), warp_n = wid>>1 (32 cols).
// MODE 0: A1 @ W1^T -> h1 (fp16 hi/lo) into A2 cols 1024..2047
// MODE 1: A2 @ WC^T -> fp32 out
// ---------------------------------------------------------------------------
template<int MODE>
__global__ void __launch_bounds__(256) gemm_kernel(
    const float* __restrict__ pb0, const float* __restrict__ pb1,
    const float* __restrict__ psc, const float* __restrict__ pbi,
    const float* __restrict__ pmu, const float* __restrict__ pva,
    float* __restrict__ outp)
{
    extern __shared__ __align__(1024) char smem[];
    const uint32_t sb = smem_u32(smem);
    const int tid = threadIdx.x;
    const int wid = tid >> 5, lane = tid & 31;
    const int warp_m = wid & 1;      // 64-row slices
    const int warp_n = wid >> 1;     // 32-col slices
    const int blockRow = blockIdx.y * BM, blockCol = blockIdx.x * BN;

    constexpr int KDIM = (MODE == 0) ? KD1 : KD2;
    constexpr int KC   = KDIM / BK;

    const __half* Ah = (MODE == 0) ? g_A1h : g_A2h;
    const __half* Al = (MODE == 0) ? g_A1l : g_A2l;
    const __half* Bh = (MODE == 0) ? g_W1  : g_WC;

    // cp.async: thread t covers row t/2 (half-row each) of all 3 planes.
    const int ldrow = tid >> 1;
    const int ldc0  = (tid & 1) * 4;
    const __half* ArH = Ah + (size_t)(blockRow + ldrow) * KDIM;
    const __half* ArL = Al + (size_t)(blockRow + ldrow) * KDIM;
    const __half* BrH = Bh + (size_t)(blockCol + ldrow) * KDIM;
    uint32_t swoff[4];
    #pragma unroll
    for (int i = 0; i < 4; i++)
        swoff[i] = sw128((uint32_t)ldrow * 128u + (uint32_t)(ldc0 + i) * 16u);

    auto load_chunk = [&](int j) {
        const char* gah = (const char*)(ArH + j * BK) + ldc0 * 16;
        const char* gal = (const char*)(ArL + j * BK) + ldc0 * 16;
        const char* gbh = (const char*)(BrH + j * BK) + ldc0 * 16;
        uint32_t bs_ = sb + (uint32_t)(j % STAGES) * STAGE_BYTES;
        #pragma unroll
        for (int i = 0; i < 4; i++) cp16(bs_ +                swoff[i], gah + i * 16);
        #pragma unroll
        for (int i = 0; i < 4; i++) cp16(bs_ + 1*TILE_BYTES + swoff[i], gal + i * 16);
        #pragma unroll
        for (int i = 0; i < 4; i++) cp16(bs_ + 2*TILE_BYTES + swoff[i], gbh + i * 16);
    };

    float acc[4][4][4] = {};    // [mtile][ntile][frag]

    const int lrow16 = lane & 15;
    const int lhalf  = lane >> 4;

    // prologue: 3 chunks in flight
    load_chunk(0); cp_commit();
    load_chunk(1); cp_commit();
    load_chunk(2); cp_commit();

    for (int i = 0; i < KC; i++) {
        cp_wait2();            // chunk i resident
        __syncthreads();
        if (i + 3 < KC) load_chunk(i + 3);
        cp_commit();

        uint32_t st  = sb + (uint32_t)(i % STAGES) * STAGE_BYTES;
        uint32_t sAh = st, sAl = st + 1*TILE_BYTES, sBh = st + 2*TILE_BYTES;

        #pragma unroll
        for (int k16 = 0; k16 < 4; k16++) {
            const uint32_t chunk = (uint32_t)(k16 * 2 + lhalf) * 16u;
            uint32_t ah[4][4], al[4][4], bh[4][2];
            #pragma unroll
            for (int it = 0; it < 4; it++) {
                uint32_t ro = sw128((uint32_t)(warp_m * 64 + it * 16 + lrow16) * 128u + chunk);
                ldm4(ah[it][0], ah[it][1], ah[it][2], ah[it][3], sAh + ro);
                ldm4(al[it][0], al[it][1], al[it][2], al[it][3], sAl + ro);
            }
            #pragma unroll
            for (int j2 = 0; j2 < 2; j2++) {
                uint32_t ro = sw128((uint32_t)(warp_n * 32 + j2 * 16 + lrow16) * 128u + chunk);
                uint32_t r0, r1, r2, r3;
                ldm4(r0, r1, r2, r3, sBh + ro);
                bh[2*j2  ][0] = r0; bh[2*j2  ][1] = r2;
                bh[2*j2+1][0] = r1; bh[2*j2+1][1] = r3;
            }
            #pragma unroll
            for (int it = 0; it < 4; it++)
                #pragma unroll
                for (int jt = 0; jt < 4; jt++) {
                    mma16816(acc[it][jt], ah[it], bh[jt]);   // Ah*Bh
                    mma16816(acc[it][jt], al[it], bh[jt]);   // Al*Bh
                }
        }
    }

    // ------------------- epilogue -------------------
    __syncthreads();
    float* sp = (float*)smem;
    if (tid < BN) {
        int n = blockCol + tid;
        float se = psc[n] * rsqrtf(pva[n] + EPSBN);
        sp[tid]           = se;
        sp[BN + tid]      = pbi[n] - pmu[n] * se;
        sp[2 * BN + tid]  = (MODE == 0) ? pb0[n] : (pb0[n] + pb1[n]);
    }
    __syncthreads();

    const int groupID = lane >> 2;
    const int colPair = (lane & 3) * 2;

    #pragma unroll
    for (int it = 0; it < 4; it++) {
        #pragma unroll
        for (int jt = 0; jt < 4; jt++) {
            int lc = warp_n * 32 + jt * 8 + colPair;
            float se0 = sp[lc],      se1 = sp[lc + 1];
            float of0 = sp[BN+lc],   of1 = sp[BN+lc+1];
            float bb0 = sp[2*BN+lc], bb1 = sp[2*BN+lc+1];
            #pragma unroll
            for (int rr = 0; rr < 2; rr++) {
                int m = blockRow + warp_m * 64 + it * 16 + groupID + rr * 8;
                float v0 = fmaf(fmaxf(acc[it][jt][2*rr]   + bb0, 0.0f), se0, of0);
                float v1 = fmaf(fmaxf(acc[it][jt][2*rr+1] + bb1, 0.0f), se1, of1);
                if (MODE == 0) {
                    __half h0, l0, h1, l1;
                    hsplit(v0, h0, l0);
                    hsplit(v1, h1, l1);
                    size_t o = (size_t)m * KD2 + 1024 + blockCol + lc;
                    *reinterpret_cast<__half2*>(&g_A2h[o]) = __halves2half2(h0, h1);
                    *reinterpret_cast<__half2*>(&g_A2l[o]) = __halves2half2(l0, l1);
                } else {
                    size_t o = (size_t)m * NOUT + blockCol + lc;
                    *reinterpret_cast<float2*>(&outp[o]) = make_float2(v0, v1);
                }
            }
        }
    }
}

// ---------------------------------------------------------------------------
// Launch (no static guards — identical work on every call)
// ---------------------------------------------------------------------------
extern "C" void kernel_launch(void* const* d_in, const int* in_sizes, int n_in,
                              void* d_out, int out_size) {
    const float* x    = (const float*)d_in[0];
    const float* q1   = (const float*)d_in[1];   // (2, bs, 512, 1): slice 0
    const float* q2   = (const float*)d_in[2];   // (4, bs, 1024,1): slice 0
    const float* w1   = (const float*)d_in[3];
    const float* b1   = (const float*)d_in[4];
    const float* w2   = (const float*)d_in[5];
    const float* b2   = (const float*)d_in[6];
    const float* wsk  = (const float*)d_in[7];
    const float* bsk  = (const float*)d_in[8];
    const float* s1   = (const float*)d_in[9];
    const float* bi1  = (const float*)d_in[10];
    const float* mu1  = (const float*)d_in[11];
    const float* va1  = (const float*)d_in[12];
    const float* s2   = (const float*)d_in[13];
    const float* bi2  = (const float*)d_in[14];
    const float* mu2  = (const float*)d_in[15];
    const float* va2  = (const float*)d_in[16];
    float* out = (float*)d_out;
    (void)in_sizes; (void)n_in; (void)out_size;

    cudaFuncSetAttribute(gemm_kernel<0>, cudaFuncAttributeMaxDynamicSharedMemorySize, SMEM_BYTES);
    cudaFuncSetAttribute(gemm_kernel<1>, cudaFuncAttributeMaxDynamicSharedMemorySize, SMEM_BYTES);

    pack_all<<<(NPTOT + 255) / 256, 256>>>(q1, x, q2, w1, w2, wsk);

    dim3 g1(NMID / BN, BSZ / BM);   // (8, 128)
    gemm_kernel<0><<<g1, 256, SMEM_BYTES>>>(b1, nullptr, s1, bi1, mu1, va1, nullptr);

    dim3 g2(NOUT / BN, BSZ / BM);   // (4, 128)
    gemm_kernel<1><<<g2, 256, SMEM_BYTES>>>(b2, bsk, s2, bi2, mu2, va2, out);
}

// round 12
// speedup vs baseline: 4.8853x; 1.6907x over previous
#include <cuda_runtime.h>
#include <cuda_fp16.h>
#include <stdint.h>

// Shapes: bs=16384, din=512, mid=1024, out=512, K=2, D1=2, D2=4
//
// Two plain-fp16 GEMMs via mma.sync (plain PTX under compute_103):
//   A1 (bs x 1024)  = interleave(q1_0, x)          [single fp16 plane]
//   h1 (bs x 1024)  = bn1(relu(A1 @ w1^T + b1))    [stored fp16]
//   A2 (bs x 3072)  = [q2_0 | h1 | A1]             (K-reordered)
//   WC (512 x 3072) = [w2 even | w2 odd | w_skip]  [single fp16 plane]
//   out (bs x 512)  = bn2(relu(A2 @ WC^T + b2 + b_skip))
// fp16 rounding on both operands -> rel_err ~3.5-4.5e-4 (< 1e-3 gate).

#define BSZ   16384
#define KD1   1024
#define KD2   3072
#define NMID  1024
#define NOUT  512
#define EPSBN 1e-5f

#define BM 128
#define BN 128
#define BK 64                           // fp16 elems -> 128B rows
#define STAGES 4
#define TILE_BYTES  (128 * 128)         // 16 KB per plane (128 rows x 128 B)
#define STAGE_BYTES (2 * TILE_BYTES)    // A | B = 32 KB
#define SMEM_BYTES  (STAGES * STAGE_BYTES)   // 128 KB

// ---------------------------------------------------------------------------
// Scratch (static device arrays: allocation-free)
// ---------------------------------------------------------------------------
static __device__ __half g_A1[(size_t)BSZ*KD1];
static __device__ __half g_A2[(size_t)BSZ*KD2];
static __device__ __half g_W1[(size_t)NMID*KD1];
static __device__ __half g_WC[(size_t)NOUT*KD2];

// ---------------------------------------------------------------------------
// PTX helpers (plain sm_80-era PTX)
// ---------------------------------------------------------------------------
__device__ __forceinline__ uint32_t smem_u32(const void* p) {
    uint32_t a;
    asm("{ .reg .u64 t; cvta.to.shared.u64 t, %1; cvt.u32.u64 %0, t; }" : "=r"(a) : "l"(p));
    return a;
}
__device__ __forceinline__ void cp16(uint32_t s, const void* g) {
    asm volatile("cp.async.cg.shared.global [%0], [%1], 16;" :: "r"(s), "l"(g));
}
__device__ __forceinline__ void cp_commit() {
    asm volatile("cp.async.commit_group;" ::: "memory");
}
__device__ __forceinline__ void cp_wait2() {
    asm volatile("cp.async.wait_group 2;" ::: "memory");
}
__device__ __forceinline__ void ldm4(uint32_t& r0, uint32_t& r1, uint32_t& r2, uint32_t& r3,
                                     uint32_t addr) {
    asm volatile("ldmatrix.sync.aligned.m8n8.x4.shared.b16 {%0,%1,%2,%3}, [%4];"
                 : "=r"(r0), "=r"(r1), "=r"(r2), "=r"(r3) : "r"(addr));
}
__device__ __forceinline__ void mma16816(float* c, const uint32_t* a, const uint32_t* b) {
    asm volatile("mma.sync.aligned.m16n8k16.row.col.f32.f16.f16.f32 "
                 "{%0,%1,%2,%3}, {%4,%5,%6,%7}, {%8,%9}, {%0,%1,%2,%3};"
                 : "+f"(c[0]), "+f"(c[1]), "+f"(c[2]), "+f"(c[3])
                 : "r"(a[0]), "r"(a[1]), "r"(a[2]), "r"(a[3]), "r"(b[0]), "r"(b[1]));
}
__device__ __forceinline__ uint32_t sw128(uint32_t o) { return o ^ ((o >> 3) & 0x70); }

// ---------------------------------------------------------------------------
// Single merged pack kernel, range-partitioned
// ---------------------------------------------------------------------------
#define NP0 (BSZ * 512)           // a1 pairs (q1, x)
#define NP1 (BSZ * 512)           // q2 float2s
#define NP2 (NMID * KD1 / 2)      // w1 float2s
#define NP3 (NOUT * KD2)          // wcat singles
#define NPTOT (NP0 + NP1 + NP2 + NP3)

__global__ void pack_all(const float* __restrict__ q1, const float* __restrict__ x,
                         const float* __restrict__ q2, const float* __restrict__ w1,
                         const float* __restrict__ w2, const float* __restrict__ wsk) {
    int i = blockIdx.x * blockDim.x + threadIdx.x;
    if (i < NP0) {
        // A1[m,2c]=q1_0[m,c], A1[m,2c+1]=x[m,c]; also copy to A2 cols 2048+
        int m = i >> 9, c = i & 511;
        __half2 hp = __halves2half2(__float2half_rn(q1[i]), __float2half_rn(x[i]));
        *reinterpret_cast<__half2*>(&g_A1[(size_t)m * KD1 + 2 * c]) = hp;
        *reinterpret_cast<__half2*>(&g_A2[(size_t)m * KD2 + 2048 + 2 * c]) = hp;
    } else if (i < NP0 + NP1) {
        int j = i - NP0;
        int m = j >> 9, c2 = (j & 511) * 2;
        float2 v = reinterpret_cast<const float2*>(q2)[j];
        *reinterpret_cast<__half2*>(&g_A2[(size_t)m * KD2 + c2]) =
            __halves2half2(__float2half_rn(v.x), __float2half_rn(v.y));
    } else if (i < NP0 + NP1 + NP2) {
        int j = i - NP0 - NP1;
        float2 v = reinterpret_cast<const float2*>(w1)[j];
        *reinterpret_cast<__half2*>(&g_W1[2*j]) =
            __halves2half2(__float2half_rn(v.x), __float2half_rn(v.y));
    } else if (i < NPTOT) {
        int j = i - NP0 - NP1 - NP2;
        int n = j / KD2, c = j - n * KD2;
        float v;
        if (c < 1024)       v = w2[(size_t)n * 2048 + 2 * c];               // pairs q2
        else if (c < 2048)  v = w2[(size_t)n * 2048 + 2 * (c - 1024) + 1];  // pairs h1
        else                v = wsk[(size_t)n * 1024 + (c - 2048)];         // skip
        g_WC[j] = __float2half_rn(v);
    }
}

// ---------------------------------------------------------------------------
// fp16 mma.sync GEMM: 128x128 CTA, BK=64, 4-stage cp.async pipeline.
// 8 warps: warp_m = wid&1 (64 rows), warp_n = wid>>1 (32 cols).
// MODE 0: A1 @ W1^T -> h1 (fp16) into A2 cols 1024..2047
// MODE 1: A2 @ WC^T -> fp32 out
// ---------------------------------------------------------------------------
template<int MODE>
__global__ void __launch_bounds__(256) gemm_kernel(
    const float* __restrict__ pb0, const float* __restrict__ pb1,
    const float* __restrict__ psc, const float* __restrict__ pbi,
    const float* __restrict__ pmu, const float* __restrict__ pva,
    float* __restrict__ outp)
{
    extern __shared__ __align__(1024) char smem[];
    const uint32_t sb = smem_u32(smem);
    const int tid = threadIdx.x;
    const int wid = tid >> 5, lane = tid & 31;
    const int warp_m = wid & 1;      // 64-row slices
    const int warp_n = wid >> 1;     // 32-col slices
    const int blockRow = blockIdx.y * BM, blockCol = blockIdx.x * BN;

    constexpr int KDIM = (MODE == 0) ? KD1 : KD2;
    constexpr int KC   = KDIM / BK;

    const __half* A = (MODE == 0) ? g_A1 : g_A2;
    const __half* B = (MODE == 0) ? g_W1 : g_WC;

    // cp.async: thread t covers row t/2 (half-row each) of both planes.
    const int ldrow = tid >> 1;
    const int ldc0  = (tid & 1) * 4;
    const __half* Ar = A + (size_t)(blockRow + ldrow) * KDIM;
    const __half* Br = B + (size_t)(blockCol + ldrow) * KDIM;
    uint32_t swoff[4];
    #pragma unroll
    for (int i = 0; i < 4; i++)
        swoff[i] = sw128((uint32_t)ldrow * 128u + (uint32_t)(ldc0 + i) * 16u);

    auto load_chunk = [&](int j) {
        const char* ga = (const char*)(Ar + j * BK) + ldc0 * 16;
        const char* gb = (const char*)(Br + j * BK) + ldc0 * 16;
        uint32_t bs_ = sb + (uint32_t)(j % STAGES) * STAGE_BYTES;
        #pragma unroll
        for (int i = 0; i < 4; i++) cp16(bs_ +              swoff[i], ga + i * 16);
        #pragma unroll
        for (int i = 0; i < 4; i++) cp16(bs_ + TILE_BYTES + swoff[i], gb + i * 16);
    };

    float acc[4][4][4] = {};    // [mtile][ntile][frag]

    const int lrow16 = lane & 15;
    const int lhalf  = lane >> 4;

    // prologue: 3 chunks in flight
    load_chunk(0); cp_commit();
    load_chunk(1); cp_commit();
    load_chunk(2); cp_commit();

    for (int i = 0; i < KC; i++) {
        cp_wait2();            // chunk i resident
        __syncthreads();
        if (i + 3 < KC) load_chunk(i + 3);
        cp_commit();

        uint32_t st = sb + (uint32_t)(i % STAGES) * STAGE_BYTES;
        uint32_t sA = st, sB = st + TILE_BYTES;

        #pragma unroll
        for (int k16 = 0; k16 < 4; k16++) {
            const uint32_t chunk = (uint32_t)(k16 * 2 + lhalf) * 16u;
            uint32_t a[4][4], b[4][2];
            #pragma unroll
            for (int it = 0; it < 4; it++) {
                uint32_t ro = sw128((uint32_t)(warp_m * 64 + it * 16 + lrow16) * 128u + chunk);
                ldm4(a[it][0], a[it][1], a[it][2], a[it][3], sA + ro);
            }
            #pragma unroll
            for (int j2 = 0; j2 < 2; j2++) {
                uint32_t ro = sw128((uint32_t)(warp_n * 32 + j2 * 16 + lrow16) * 128u + chunk);
                uint32_t r0, r1, r2, r3;
                ldm4(r0, r1, r2, r3, sB + ro);
                b[2*j2  ][0] = r0; b[2*j2  ][1] = r2;
                b[2*j2+1][0] = r1; b[2*j2+1][1] = r3;
            }
            #pragma unroll
            for (int it = 0; it < 4; it++)
                #pragma unroll
                for (int jt = 0; jt < 4; jt++)
                    mma16816(acc[it][jt], a[it], b[jt]);
        }
    }

    // ------------------- epilogue -------------------
    __syncthreads();
    float* sp = (float*)smem;
    if (tid < BN) {
        int n = blockCol + tid;
        float se = psc[n] * rsqrtf(pva[n] + EPSBN);
        sp[tid]           = se;
        sp[BN + tid]      = pbi[n] - pmu[n] * se;
        sp[2 * BN + tid]  = (MODE == 0) ? pb0[n] : (pb0[n] + pb1[n]);
    }
    __syncthreads();

    const int groupID = lane >> 2;
    const int colPair = (lane & 3) * 2;

    #pragma unroll
    for (int it = 0; it < 4; it++) {
        #pragma unroll
        for (int jt = 0; jt < 4; jt++) {
            int lc = warp_n * 32 + jt * 8 + colPair;
            float se0 = sp[lc],      se1 = sp[lc + 1];
            float of0 = sp[BN+lc],   of1 = sp[BN+lc+1];
            float bb0 = sp[2*BN+lc], bb1 = sp[2*BN+lc+1];
            #pragma unroll
            for (int rr = 0; rr < 2; rr++) {
                int m = blockRow + warp_m * 64 + it * 16 + groupID + rr * 8;
                float v0 = fmaf(fmaxf(acc[it][jt][2*rr]   + bb0, 0.0f), se0, of0);
                float v1 = fmaf(fmaxf(acc[it][jt][2*rr+1] + bb1, 0.0f), se1, of1);
                if (MODE == 0) {
                    size_t o = (size_t)m * KD2 + 1024 + blockCol + lc;
                    *reinterpret_cast<__half2*>(&g_A2[o]) =
                        __halves2half2(__float2half_rn(v0), __float2half_rn(v1));
                } else {
                    size_t o = (size_t)m * NOUT + blockCol + lc;
                    *reinterpret_cast<float2*>(&outp[o]) = make_float2(v0, v1);
                }
            }
        }
    }
}

// ---------------------------------------------------------------------------
// Launch (no static guards — identical work on every call)
// ---------------------------------------------------------------------------
extern "C" void kernel_launch(void* const* d_in, const int* in_sizes, int n_in,
                              void* d_out, int out_size) {
    const float* x    = (const float*)d_in[0];
    const float* q1   = (const float*)d_in[1];   // (2, bs, 512, 1): slice 0
    const float* q2   = (const float*)d_in[2];   // (4, bs, 1024,1): slice 0
    const float* w1   = (const float*)d_in[3];
    const float* b1   = (const float*)d_in[4];
    const float* w2   = (const float*)d_in[5];
    const float* b2   = (const float*)d_in[6];
    const float* wsk  = (const float*)d_in[7];
    const float* bsk  = (const float*)d_in[8];
    const float* s1   = (const float*)d_in[9];
    const float* bi1  = (const float*)d_in[10];
    const float* mu1  = (const float*)d_in[11];
    const float* va1  = (const float*)d_in[12];
    const float* s2   = (const float*)d_in[13];
    const float* bi2  = (const float*)d_in[14];
    const float* mu2  = (const float*)d_in[15];
    const float* va2  = (const float*)d_in[16];
    float* out = (float*)d_out;
    (void)in_sizes; (void)n_in; (void)out_size;

    cudaFuncSetAttribute(gemm_kernel<0>, cudaFuncAttributeMaxDynamicSharedMemorySize, SMEM_BYTES);
    cudaFuncSetAttribute(gemm_kernel<1>, cudaFuncAttributeMaxDynamicSharedMemorySize, SMEM_BYTES);

    pack_all<<<(NPTOT + 255) / 256, 256>>>(q1, x, q2, w1, w2, wsk);

    dim3 g1(NMID / BN, BSZ / BM);   // (8, 128)
    gemm_kernel<0><<<g1, 256, SMEM_BYTES>>>(b1, nullptr, s1, bi1, mu1, va1, nullptr);

    dim3 g2(NOUT / BN, BSZ / BM);   // (4, 128)
    gemm_kernel<1><<<g2, 256, SMEM_BYTES>>>(b2, bsk, s2, bi2, mu2, va2, out);
}

// round 13
// speedup vs baseline: 5.1145x; 1.0469x over previous
#include <cuda_runtime.h>
#include <cuda_fp16.h>
#include <stdint.h>

// Shapes: bs=16384, din=512, mid=1024, out=512, K=2, D1=2, D2=4
//
// Two plain-fp16 GEMMs via mma.sync (plain PTX under compute_103):
//   A1 (bs x 1024)  = interleave(q1_0, x)           [fp16]
//   h1 (bs x 1024)  = bn1(relu(A1 @ w1^T + b1))     [fp16]
//   GEMM2 K=3072 reads 3 segments DIRECTLY (no concat buffer):
//       seg0 = q2_0 (fp16)   seg1 = h1   seg2 = A1      (all row-stride 1024)
//   WC (512 x 3072) = [w2 even | w2 odd | w_skip]   [fp16]
//   out (bs x 512)  = bn2(relu(A2 @ WC^T + b2 + b_skip))

#define BSZ   16384
#define KD1   1024
#define KD2   3072
#define NMID  1024
#define NOUT  512
#define EPSBN 1e-5f

#define BM 128
#define BN 128
#define BK 64                           // fp16 elems -> 128B rows
#define STAGES 4
#define TILE_BYTES  (128 * 128)         // 16 KB per plane
#define STAGE_BYTES (2 * TILE_BYTES)    // A | B = 32 KB
#define SMEM_BYTES  (STAGES * STAGE_BYTES)   // 128 KB

// ---------------------------------------------------------------------------
// Scratch (static device arrays: allocation-free)
// ---------------------------------------------------------------------------
static __device__ __half g_A1[(size_t)BSZ*KD1];
static __device__ __half g_Q2[(size_t)BSZ*KD1];
static __device__ __half g_H1[(size_t)BSZ*KD1];
static __device__ __half g_W1[(size_t)NMID*KD1];
static __device__ __half g_WC[(size_t)NOUT*KD2];

// ---------------------------------------------------------------------------
// PTX helpers (plain sm_80-era PTX)
// ---------------------------------------------------------------------------
__device__ __forceinline__ uint32_t smem_u32(const void* p) {
    uint32_t a;
    asm("{ .reg .u64 t; cvta.to.shared.u64 t, %1; cvt.u32.u64 %0, t; }" : "=r"(a) : "l"(p));
    return a;
}
__device__ __forceinline__ void cp16(uint32_t s, const void* g) {
    asm volatile("cp.async.cg.shared.global [%0], [%1], 16;" :: "r"(s), "l"(g));
}
__device__ __forceinline__ void cp_commit() {
    asm volatile("cp.async.commit_group;" ::: "memory");
}
__device__ __forceinline__ void cp_wait2() {
    asm volatile("cp.async.wait_group 2;" ::: "memory");
}
__device__ __forceinline__ void ldm4(uint32_t& r0, uint32_t& r1, uint32_t& r2, uint32_t& r3,
                                     uint32_t addr) {
    asm volatile("ldmatrix.sync.aligned.m8n8.x4.shared.b16 {%0,%1,%2,%3}, [%4];"
                 : "=r"(r0), "=r"(r1), "=r"(r2), "=r"(r3) : "r"(addr));
}
__device__ __forceinline__ void mma16816(float* c, const uint32_t* a, const uint32_t* b) {
    asm volatile("mma.sync.aligned.m16n8k16.row.col.f32.f16.f16.f32 "
                 "{%0,%1,%2,%3}, {%4,%5,%6,%7}, {%8,%9}, {%0,%1,%2,%3};"
                 : "+f"(c[0]), "+f"(c[1]), "+f"(c[2]), "+f"(c[3])
                 : "r"(a[0]), "r"(a[1]), "r"(a[2]), "r"(a[3]), "r"(b[0]), "r"(b[1]));
}
__device__ __forceinline__ uint32_t sw128(uint32_t o) { return o ^ ((o >> 3) & 0x70); }

__device__ __forceinline__ uint32_t h2u(float a, float b) {
    union { __half2 h; uint32_t u; } U;
    U.h = __halves2half2(__float2half_rn(a), __float2half_rn(b));
    return U.u;
}

// ---------------------------------------------------------------------------
// Merged pack kernel (vectorized, range-partitioned)
// ---------------------------------------------------------------------------
#define NP0 (BSZ * 256)           // A1: 4-elem granules (2 q1 + 2 x)
#define NP1 (BSZ * 256)           // q2: float4 granules
#define NP2 (NMID * KD1 / 4)      // w1: float4 granules
#define NP3 (NOUT * KD2)          // wcat singles (gather)
#define NPTOT (NP0 + NP1 + NP2 + NP3)

__global__ void pack_all(const float* __restrict__ q1, const float* __restrict__ x,
                         const float* __restrict__ q2, const float* __restrict__ w1,
                         const float* __restrict__ w2, const float* __restrict__ wsk) {
    int i = blockIdx.x * blockDim.x + threadIdx.x;
    if (i < NP0) {
        // A1[m, 4t..4t+3] = q1[m,2t], x[m,2t], q1[m,2t+1], x[m,2t+1]
        int m = i >> 8, t = i & 255;
        float2 a = reinterpret_cast<const float2*>(q1)[(size_t)m * 256 + t];
        float2 b = reinterpret_cast<const float2*>(x )[(size_t)m * 256 + t];
        uint2 st = make_uint2(h2u(a.x, b.x), h2u(a.y, b.y));
        *reinterpret_cast<uint2*>(&g_A1[(size_t)m * KD1 + 4 * t]) = st;
    } else if (i < NP0 + NP1) {
        int j = i - NP0;
        int m = j >> 8, t = j & 255;
        float4 v = reinterpret_cast<const float4*>(q2)[(size_t)m * 256 + t];
        uint2 st = make_uint2(h2u(v.x, v.y), h2u(v.z, v.w));
        *reinterpret_cast<uint2*>(&g_Q2[(size_t)m * KD1 + 4 * t]) = st;
    } else if (i < NP0 + NP1 + NP2) {
        int j = i - NP0 - NP1;
        float4 v = reinterpret_cast<const float4*>(w1)[j];
        uint2 st = make_uint2(h2u(v.x, v.y), h2u(v.z, v.w));
        *reinterpret_cast<uint2*>(&g_W1[(size_t)4 * j]) = st;
    } else if (i < NPTOT) {
        int j = i - NP0 - NP1 - NP2;
        int n = j / KD2, c = j - n * KD2;
        float v;
        if (c < 1024)       v = w2[(size_t)n * 2048 + 2 * c];               // pairs q2
        else if (c < 2048)  v = w2[(size_t)n * 2048 + 2 * (c - 1024) + 1];  // pairs h1
        else                v = wsk[(size_t)n * 1024 + (c - 2048)];         // skip
        g_WC[j] = __float2half_rn(v);
    }
}

// ---------------------------------------------------------------------------
// fp16 mma.sync GEMM: 128x128 CTA, BK=64, 4-stage cp.async pipeline.
// 8 warps: warp_m = wid&1 (64 rows), warp_n = wid>>1 (32 cols).
// MODE 0: A1 @ W1^T -> h1 (fp16) into g_H1
// MODE 1: [q2|h1|A1] @ WC^T -> fp32 out   (per-chunk segment pointer select)
// ---------------------------------------------------------------------------
template<int MODE>
__global__ void __launch_bounds__(256) gemm_kernel(
    const float* __restrict__ pb0, const float* __restrict__ pb1,
    const float* __restrict__ psc, const float* __restrict__ pbi,
    const float* __restrict__ pmu, const float* __restrict__ pva,
    float* __restrict__ outp)
{
    extern __shared__ __align__(1024) char smem[];
    const uint32_t sb = smem_u32(smem);
    const int tid = threadIdx.x;
    const int wid = tid >> 5, lane = tid & 31;
    const int warp_m = wid & 1;      // 64-row slices
    const int warp_n = wid >> 1;     // 32-col slices
    const int blockRow = blockIdx.y * BM, blockCol = blockIdx.x * BN;

    constexpr int KC    = (MODE == 0) ? (KD1 / BK) : (KD2 / BK);   // 16 / 48
    constexpr int KDIMB = (MODE == 0) ? KD1 : KD2;                 // B row stride

    // cp.async: thread t covers row t/2 (half-row each) of both planes.
    const int ldrow = tid >> 1;
    const int ldc0  = (tid & 1) * 4;
    // A-plane row bases (all segments have row stride KD1)
    const char* pA1c = (const char*)(g_A1 + (size_t)(blockRow + ldrow) * KD1) + ldc0 * 16;
    const char* pQ2c = (const char*)(g_Q2 + (size_t)(blockRow + ldrow) * KD1) + ldc0 * 16;
    const char* pH1c = (const char*)(g_H1 + (size_t)(blockRow + ldrow) * KD1) + ldc0 * 16;
    const __half* Bg = (MODE == 0) ? g_W1 : g_WC;
    const char* pBc  = (const char*)(Bg + (size_t)(blockCol + ldrow) * KDIMB) + ldc0 * 16;

    uint32_t swoff[4];
    #pragma unroll
    for (int i = 0; i < 4; i++)
        swoff[i] = sw128((uint32_t)ldrow * 128u + (uint32_t)(ldc0 + i) * 16u);

    auto load_chunk = [&](int j) {
        const char* ga;
        if (MODE == 0) {
            ga = pA1c + (size_t)j * 128;
        } else {
            int seg = j >> 4, kc = j & 15;    // 16 chunks per 1024-col segment
            const char* base = (seg == 0) ? pQ2c : ((seg == 1) ? pH1c : pA1c);
            ga = base + (size_t)kc * 128;
        }
        const char* gb = pBc + (size_t)j * 128;
        uint32_t bs_ = sb + (uint32_t)(j % STAGES) * STAGE_BYTES;
        #pragma unroll
        for (int i = 0; i < 4; i++) cp16(bs_ +              swoff[i], ga + i * 16);
        #pragma unroll
        for (int i = 0; i < 4; i++) cp16(bs_ + TILE_BYTES + swoff[i], gb + i * 16);
    };

    float acc[4][4][4] = {};    // [mtile][ntile][frag]

    const int lrow16 = lane & 15;
    const int lhalf  = lane >> 4;

    // prologue: 3 chunks in flight
    load_chunk(0); cp_commit();
    load_chunk(1); cp_commit();
    load_chunk(2); cp_commit();

    for (int i = 0; i < KC; i++) {
        cp_wait2();            // chunk i resident
        __syncthreads();
        if (i + 3 < KC) load_chunk(i + 3);
        cp_commit();

        uint32_t st = sb + (uint32_t)(i % STAGES) * STAGE_BYTES;
        uint32_t sA = st, sB = st + TILE_BYTES;

        #pragma unroll
        for (int k16 = 0; k16 < 4; k16++) {
            const uint32_t chunk = (uint32_t)(k16 * 2 + lhalf) * 16u;
            uint32_t a[4][4], b[4][2];
            #pragma unroll
            for (int it = 0; it < 4; it++) {
                uint32_t ro = sw128((uint32_t)(warp_m * 64 + it * 16 + lrow16) * 128u + chunk);
                ldm4(a[it][0], a[it][1], a[it][2], a[it][3], sA + ro);
            }
            #pragma unroll
            for (int j2 = 0; j2 < 2; j2++) {
                uint32_t ro = sw128((uint32_t)(warp_n * 32 + j2 * 16 + lrow16) * 128u + chunk);
                uint32_t r0, r1, r2, r3;
                ldm4(r0, r1, r2, r3, sB + ro);
                b[2*j2  ][0] = r0; b[2*j2  ][1] = r2;
                b[2*j2+1][0] = r1; b[2*j2+1][1] = r3;
            }
            #pragma unroll
            for (int it = 0; it < 4; it++)
                #pragma unroll
                for (int jt = 0; jt < 4; jt++)
                    mma16816(acc[it][jt], a[it], b[jt]);
        }
    }

    // ------------------- epilogue -------------------
    __syncthreads();
    float* sp = (float*)smem;
    if (tid < BN) {
        int n = blockCol + tid;
        float se = psc[n] * rsqrtf(pva[n] + EPSBN);
        sp[tid]           = se;
        sp[BN + tid]      = pbi[n] - pmu[n] * se;
        sp[2 * BN + tid]  = (MODE == 0) ? pb0[n] : (pb0[n] + pb1[n]);
    }
    __syncthreads();

    const int groupID = lane >> 2;
    const int colPair = (lane & 3) * 2;

    #pragma unroll
    for (int it = 0; it < 4; it++) {
        #pragma unroll
        for (int jt = 0; jt < 4; jt++) {
            int lc = warp_n * 32 + jt * 8 + colPair;
            float se0 = sp[lc],      se1 = sp[lc + 1];
            float of0 = sp[BN+lc],   of1 = sp[BN+lc+1];
            float bb0 = sp[2*BN+lc], bb1 = sp[2*BN+lc+1];
            #pragma unroll
            for (int rr = 0; rr < 2; rr++) {
                int m = blockRow + warp_m * 64 + it * 16 + groupID + rr * 8;
                float v0 = fmaf(fmaxf(acc[it][jt][2*rr]   + bb0, 0.0f), se0, of0);
                float v1 = fmaf(fmaxf(acc[it][jt][2*rr+1] + bb1, 0.0f), se1, of1);
                if (MODE == 0) {
                    size_t o = (size_t)m * KD1 + blockCol + lc;
                    *reinterpret_cast<__half2*>(&g_H1[o]) =
                        __halves2half2(__float2half_rn(v0), __float2half_rn(v1));
                } else {
                    size_t o = (size_t)m * NOUT + blockCol + lc;
                    *reinterpret_cast<float2*>(&outp[o]) = make_float2(v0, v1);
                }
            }
        }
    }
}

// ---------------------------------------------------------------------------
// Launch (no static guards — identical work on every call)
// ---------------------------------------------------------------------------
extern "C" void kernel_launch(void* const* d_in, const int* in_sizes, int n_in,
                              void* d_out, int out_size) {
    const float* x    = (const float*)d_in[0];
    const float* q1   = (const float*)d_in[1];   // (2, bs, 512, 1): slice 0
    const float* q2   = (const float*)d_in[2];   // (4, bs, 1024,1): slice 0
    const float* w1   = (const float*)d_in[3];
    const float* b1   = (const float*)d_in[4];
    const float* w2   = (const float*)d_in[5];
    const float* b2   = (const float*)d_in[6];
    const float* wsk  = (const float*)d_in[7];
    const float* bsk  = (const float*)d_in[8];
    const float* s1   = (const float*)d_in[9];
    const float* bi1  = (const float*)d_in[10];
    const float* mu1  = (const float*)d_in[11];
    const float* va1  = (const float*)d_in[12];
    const float* s2   = (const float*)d_in[13];
    const float* bi2  = (const float*)d_in[14];
    const float* mu2  = (const float*)d_in[15];
    const float* va2  = (const float*)d_in[16];
    float* out = (float*)d_out;
    (void)in_sizes; (void)n_in; (void)out_size;

    cudaFuncSetAttribute(gemm_kernel<0>, cudaFuncAttributeMaxDynamicSharedMemorySize, SMEM_BYTES);
    cudaFuncSetAttribute(gemm_kernel<1>, cudaFuncAttributeMaxDynamicSharedMemorySize, SMEM_BYTES);

    pack_all<<<(NPTOT + 255) / 256, 256>>>(q1, x, q2, w1, w2, wsk);

    dim3 g1(NMID / BN, BSZ / BM);   // (8, 128)
    gemm_kernel<0><<<g1, 256, SMEM_BYTES>>>(b1, nullptr, s1, bi1, mu1, va1, nullptr);

    dim3 g2(NOUT / BN, BSZ / BM);   // (4, 128)
    gemm_kernel<1><<<g2, 256, SMEM_BYTES>>>(b2, bsk, s2, bi2, mu2, va2, out);
}

// round 14
// speedup vs baseline: 5.5877x; 1.0925x over previous
#include <cuda_runtime.h>
#include <cuda_fp16.h>
#include <stdint.h>

// Shapes: bs=16384, din=512, mid=1024, out=512, K=2, D1=2, D2=4
//
// Two plain-fp16 GEMMs via mma.sync (plain PTX under compute_103):
//   A1 (bs x 1024)  = interleave(q1_0, x)           [fp16]
//   h1 (bs x 1024)  = bn1(relu(A1 @ w1^T + b1))     [fp16]
//   GEMM2 K=3072 reads 3 segments DIRECTLY (no concat buffer):
//       seg0 = q2_0 (fp16)   seg1 = h1   seg2 = A1      (all row-stride 1024)
//   WC (512 x 3072) = [w2 even | w2 odd | w_skip]   [fp16]
//   out (bs x 512)  = bn2(relu(A2 @ WC^T + b2 + b_skip))
// 3-stage pipeline (96 KB smem) + launch_bounds(256,2) -> 2 CTAs/SM.

#define BSZ   16384
#define KD1   1024
#define KD2   3072
#define NMID  1024
#define NOUT  512
#define EPSBN 1e-5f

#define BM 128
#define BN 128
#define BK 64                           // fp16 elems -> 128B rows
#define STAGES 3
#define TILE_BYTES  (128 * 128)         // 16 KB per plane
#define STAGE_BYTES (2 * TILE_BYTES)    // A | B = 32 KB
#define SMEM_BYTES  (STAGES * STAGE_BYTES)   // 96 KB -> 2 CTAs/SM

// ---------------------------------------------------------------------------
// Scratch (static device arrays: allocation-free)
// ---------------------------------------------------------------------------
static __device__ __half g_A1[(size_t)BSZ*KD1];
static __device__ __half g_Q2[(size_t)BSZ*KD1];
static __device__ __half g_H1[(size_t)BSZ*KD1];
static __device__ __half g_W1[(size_t)NMID*KD1];
static __device__ __half g_WC[(size_t)NOUT*KD2];

// ---------------------------------------------------------------------------
// PTX helpers (plain sm_80-era PTX)
// ---------------------------------------------------------------------------
__device__ __forceinline__ uint32_t smem_u32(const void* p) {
    uint32_t a;
    asm("{ .reg .u64 t; cvta.to.shared.u64 t, %1; cvt.u32.u64 %0, t; }" : "=r"(a) : "l"(p));
    return a;
}
__device__ __forceinline__ void cp16(uint32_t s, const void* g) {
    asm volatile("cp.async.cg.shared.global [%0], [%1], 16;" :: "r"(s), "l"(g));
}
__device__ __forceinline__ void cp_commit() {
    asm volatile("cp.async.commit_group;" ::: "memory");
}
__device__ __forceinline__ void cp_wait1() {
    asm volatile("cp.async.wait_group 1;" ::: "memory");
}
__device__ __forceinline__ void ldm4(uint32_t& r0, uint32_t& r1, uint32_t& r2, uint32_t& r3,
                                     uint32_t addr) {
    asm volatile("ldmatrix.sync.aligned.m8n8.x4.shared.b16 {%0,%1,%2,%3}, [%4];"
                 : "=r"(r0), "=r"(r1), "=r"(r2), "=r"(r3) : "r"(addr));
}
__device__ __forceinline__ void mma16816(float* c, const uint32_t* a, const uint32_t* b) {
    asm volatile("mma.sync.aligned.m16n8k16.row.col.f32.f16.f16.f32 "
                 "{%0,%1,%2,%3}, {%4,%5,%6,%7}, {%8,%9}, {%0,%1,%2,%3};"
                 : "+f"(c[0]), "+f"(c[1]), "+f"(c[2]), "+f"(c[3])
                 : "r"(a[0]), "r"(a[1]), "r"(a[2]), "r"(a[3]), "r"(b[0]), "r"(b[1]));
}
__device__ __forceinline__ uint32_t sw128(uint32_t o) { return o ^ ((o >> 3) & 0x70); }

__device__ __forceinline__ uint32_t h2u(float a, float b) {
    union { __half2 h; uint32_t u; } U;
    U.h = __halves2half2(__float2half_rn(a), __float2half_rn(b));
    return U.u;
}

// ---------------------------------------------------------------------------
// Merged pack kernel (vectorized, range-partitioned)
// ---------------------------------------------------------------------------
#define NP0 (BSZ * 256)           // A1: 4-elem granules (2 q1 + 2 x)
#define NP1 (BSZ * 256)           // q2: float4 granules
#define NP2 (NMID * KD1 / 4)      // w1: float4 granules
#define NP3 (NOUT * KD2)          // wcat singles (gather)
#define NPTOT (NP0 + NP1 + NP2 + NP3)

__global__ void pack_all(const float* __restrict__ q1, const float* __restrict__ x,
                         const float* __restrict__ q2, const float* __restrict__ w1,
                         const float* __restrict__ w2, const float* __restrict__ wsk) {
    int i = blockIdx.x * blockDim.x + threadIdx.x;
    if (i < NP0) {
        // A1[m, 4t..4t+3] = q1[m,2t], x[m,2t], q1[m,2t+1], x[m,2t+1]
        int m = i >> 8, t = i & 255;
        float2 a = reinterpret_cast<const float2*>(q1)[(size_t)m * 256 + t];
        float2 b = reinterpret_cast<const float2*>(x )[(size_t)m * 256 + t];
        uint2 st = make_uint2(h2u(a.x, b.x), h2u(a.y, b.y));
        *reinterpret_cast<uint2*>(&g_A1[(size_t)m * KD1 + 4 * t]) = st;
    } else if (i < NP0 + NP1) {
        int j = i - NP0;
        int m = j >> 8, t = j & 255;
        float4 v = reinterpret_cast<const float4*>(q2)[(size_t)m * 256 + t];
        uint2 st = make_uint2(h2u(v.x, v.y), h2u(v.z, v.w));
        *reinterpret_cast<uint2*>(&g_Q2[(size_t)m * KD1 + 4 * t]) = st;
    } else if (i < NP0 + NP1 + NP2) {
        int j = i - NP0 - NP1;
        float4 v = reinterpret_cast<const float4*>(w1)[j];
        uint2 st = make_uint2(h2u(v.x, v.y), h2u(v.z, v.w));
        *reinterpret_cast<uint2*>(&g_W1[(size_t)4 * j]) = st;
    } else if (i < NPTOT) {
        int j = i - NP0 - NP1 - NP2;
        int n = j / KD2, c = j - n * KD2;
        float v;
        if (c < 1024)       v = w2[(size_t)n * 2048 + 2 * c];               // pairs q2
        else if (c < 2048)  v = w2[(size_t)n * 2048 + 2 * (c - 1024) + 1];  // pairs h1
        else                v = wsk[(size_t)n * 1024 + (c - 2048)];         // skip
        g_WC[j] = __float2half_rn(v);
    }
}

// ---------------------------------------------------------------------------
// fp16 mma.sync GEMM: 128x128 CTA, BK=64, 3-stage cp.async pipeline, 2 CTAs/SM.
// 8 warps: warp_m = wid&1 (64 rows), warp_n = wid>>1 (32 cols).
// MODE 0: A1 @ W1^T -> h1 (fp16) into g_H1
// MODE 1: [q2|h1|A1] @ WC^T -> fp32 out   (per-chunk segment pointer select)
// ---------------------------------------------------------------------------
template<int MODE>
__global__ void __launch_bounds__(256, 2) gemm_kernel(
    const float* __restrict__ pb0, const float* __restrict__ pb1,
    const float* __restrict__ psc, const float* __restrict__ pbi,
    const float* __restrict__ pmu, const float* __restrict__ pva,
    float* __restrict__ outp)
{
    extern __shared__ __align__(1024) char smem[];
    const uint32_t sb = smem_u32(smem);
    const int tid = threadIdx.x;
    const int wid = tid >> 5, lane = tid & 31;
    const int warp_m = wid & 1;      // 64-row slices
    const int warp_n = wid >> 1;     // 32-col slices
    const int blockRow = blockIdx.y * BM, blockCol = blockIdx.x * BN;

    constexpr int KC    = (MODE == 0) ? (KD1 / BK) : (KD2 / BK);   // 16 / 48
    constexpr int KDIMB = (MODE == 0) ? KD1 : KD2;                 // B row stride

    // cp.async: thread t covers row t/2 (half-row each) of both planes.
    const int ldrow = tid >> 1;
    const int ldc0  = (tid & 1) * 4;
    // A-plane row bases (all segments have row stride KD1)
    const char* pA1c = (const char*)(g_A1 + (size_t)(blockRow + ldrow) * KD1) + ldc0 * 16;
    const char* pQ2c = (const char*)(g_Q2 + (size_t)(blockRow + ldrow) * KD1) + ldc0 * 16;
    const char* pH1c = (const char*)(g_H1 + (size_t)(blockRow + ldrow) * KD1) + ldc0 * 16;
    const __half* Bg = (MODE == 0) ? g_W1 : g_WC;
    const char* pBc  = (const char*)(Bg + (size_t)(blockCol + ldrow) * KDIMB) + ldc0 * 16;

    uint32_t swoff[4];
    #pragma unroll
    for (int i = 0; i < 4; i++)
        swoff[i] = sw128((uint32_t)ldrow * 128u + (uint32_t)(ldc0 + i) * 16u);

    auto load_chunk = [&](int j) {
        const char* ga;
        if (MODE == 0) {
            ga = pA1c + (size_t)j * 128;
        } else {
            int seg = j >> 4, kc = j & 15;    // 16 chunks per 1024-col segment
            const char* base = (seg == 0) ? pQ2c : ((seg == 1) ? pH1c : pA1c);
            ga = base + (size_t)kc * 128;
        }
        const char* gb = pBc + (size_t)j * 128;
        uint32_t bs_ = sb + (uint32_t)(j % STAGES) * STAGE_BYTES;
        #pragma unroll
        for (int i = 0; i < 4; i++) cp16(bs_ +              swoff[i], ga + i * 16);
        #pragma unroll
        for (int i = 0; i < 4; i++) cp16(bs_ + TILE_BYTES + swoff[i], gb + i * 16);
    };

    float acc[4][4][4] = {};    // [mtile][ntile][frag]

    const int lrow16 = lane & 15;
    const int lhalf  = lane >> 4;

    // prologue: 2 chunks in flight
    load_chunk(0); cp_commit();
    load_chunk(1); cp_commit();

    for (int i = 0; i < KC; i++) {
        cp_wait1();            // chunk i resident
        __syncthreads();
        if (i + 2 < KC) load_chunk(i + 2);
        cp_commit();

        uint32_t st = sb + (uint32_t)(i % STAGES) * STAGE_BYTES;
        uint32_t sA = st, sB = st + TILE_BYTES;

        #pragma unroll
        for (int k16 = 0; k16 < 4; k16++) {
            const uint32_t chunk = (uint32_t)(k16 * 2 + lhalf) * 16u;
            uint32_t a[4][4], b[4][2];
            #pragma unroll
            for (int it = 0; it < 4; it++) {
                uint32_t ro = sw128((uint32_t)(warp_m * 64 + it * 16 + lrow16) * 128u + chunk);
                ldm4(a[it][0], a[it][1], a[it][2], a[it][3], sA + ro);
            }
            #pragma unroll
            for (int j2 = 0; j2 < 2; j2++) {
                uint32_t ro = sw128((uint32_t)(warp_n * 32 + j2 * 16 + lrow16) * 128u + chunk);
                uint32_t r0, r1, r2, r3;
                ldm4(r0, r1, r2, r3, sB + ro);
                b[2*j2  ][0] = r0; b[2*j2  ][1] = r2;
                b[2*j2+1][0] = r1; b[2*j2+1][1] = r3;
            }
            #pragma unroll
            for (int it = 0; it < 4; it++)
                #pragma unroll
                for (int jt = 0; jt < 4; jt++)
                    mma16816(acc[it][jt], a[it], b[jt]);
        }
    }

    // ------------------- epilogue -------------------
    __syncthreads();
    float* sp = (float*)smem;
    if (tid < BN) {
        int n = blockCol + tid;
        float se = psc[n] * rsqrtf(pva[n] + EPSBN);
        sp[tid]           = se;
        sp[BN + tid]      = pbi[n] - pmu[n] * se;
        sp[2 * BN + tid]  = (MODE == 0) ? pb0[n] : (pb0[n] + pb1[n]);
    }
    __syncthreads();

    const int groupID = lane >> 2;
    const int colPair = (lane & 3) * 2;

    #pragma unroll
    for (int it = 0; it < 4; it++) {
        #pragma unroll
        for (int jt = 0; jt < 4; jt++) {
            int lc = warp_n * 32 + jt * 8 + colPair;
            float se0 = sp[lc],      se1 = sp[lc + 1];
            float of0 = sp[BN+lc],   of1 = sp[BN+lc+1];
            float bb0 = sp[2*BN+lc], bb1 = sp[2*BN+lc+1];
            #pragma unroll
            for (int rr = 0; rr < 2; rr++) {
                int m = blockRow + warp_m * 64 + it * 16 + groupID + rr * 8;
                float v0 = fmaf(fmaxf(acc[it][jt][2*rr]   + bb0, 0.0f), se0, of0);
                float v1 = fmaf(fmaxf(acc[it][jt][2*rr+1] + bb1, 0.0f), se1, of1);
                if (MODE == 0) {
                    size_t o = (size_t)m * KD1 + blockCol + lc;
                    *reinterpret_cast<__half2*>(&g_H1[o]) =
                        __halves2half2(__float2half_rn(v0), __float2half_rn(v1));
                } else {
                    size_t o = (size_t)m * NOUT + blockCol + lc;
                    *reinterpret_cast<float2*>(&outp[o]) = make_float2(v0, v1);
                }
            }
        }
    }
}

// ---------------------------------------------------------------------------
// Launch (no static guards — identical work on every call)
// ---------------------------------------------------------------------------
extern "C" void kernel_launch(void* const* d_in, const int* in_sizes, int n_in,
                              void* d_out, int out_size) {
    const float* x    = (const float*)d_in[0];
    const float* q1   = (const float*)d_in[1];   // (2, bs, 512, 1): slice 0
    const float* q2   = (const float*)d_in[2];   // (4, bs, 1024,1): slice 0
    const float* w1   = (const float*)d_in[3];
    const float* b1   = (const float*)d_in[4];
    const float* w2   = (const float*)d_in[5];
    const float* b2   = (const float*)d_in[6];
    const float* wsk  = (const float*)d_in[7];
    const float* bsk  = (const float*)d_in[8];
    const float* s1   = (const float*)d_in[9];
    const float* bi1  = (const float*)d_in[10];
    const float* mu1  = (const float*)d_in[11];
    const float* va1  = (const float*)d_in[12];
    const float* s2   = (const float*)d_in[13];
    const float* bi2  = (const float*)d_in[14];
    const float* mu2  = (const float*)d_in[15];
    const float* va2  = (const float*)d_in[16];
    float* out = (float*)d_out;
    (void)in_sizes; (void)n_in; (void)out_size;

    cudaFuncSetAttribute(gemm_kernel<0>, cudaFuncAttributeMaxDynamicSharedMemorySize, SMEM_BYTES);
    cudaFuncSetAttribute(gemm_kernel<1>, cudaFuncAttributeMaxDynamicSharedMemorySize, SMEM_BYTES);

    pack_all<<<(NPTOT + 255) / 256, 256>>>(q1, x, q2, w1, w2, wsk);

    dim3 g1(NMID / BN, BSZ / BM);   // (8, 128)
    gemm_kernel<0><<<g1, 256, SMEM_BYTES>>>(b1, nullptr, s1, bi1, mu1, va1, nullptr);

    dim3 g2(NOUT / BN, BSZ / BM);   // (4, 128)
    gemm_kernel<1><<<g2, 256, SMEM_BYTES>>>(b2, bsk, s2, bi2, mu2, va2, out);
}

// round 16
// speedup vs baseline: 5.7054x; 1.0211x over previous
#include <cuda_runtime.h>
#include <cuda_fp16.h>
#include <stdint.h>

// Shapes: bs=16384, din=512, mid=1024, out=512, K=2, D1=2, D2=4
//
// Two plain-fp16 GEMMs via mma.sync (plain PTX under compute_103):
//   A1 (bs x 1024)  = interleave(q1_0, x)           [fp16]
//   h1 (bs x 1024)  = bn1(relu(A1 @ w1^T + b1))     [fp16]
//   GEMM2 K=3072 reads 3 segments DIRECTLY (no concat buffer):
//       seg0 = q2_0 (fp16)   seg1 = h1   seg2 = A1      (all row-stride 1024)
//   WC (512 x 3072) = [w2 even | w2 odd | w_skip]   [fp16]
//   out (bs x 512)  = bn2(relu(A2 @ WC^T + b2 + b_skip))
// 3-stage pipeline (96 KB smem) + launch_bounds(256,2) -> 2 CTAs/SM.

#define BSZ   16384
#define KD1   1024
#define KD2   3072
#define NMID  1024
#define NOUT  512
#define EPSBN 1e-5f

#define BM 128
#define BN 128
#define BK 64                           // fp16 elems -> 128B rows
#define STAGES 3
#define TILE_BYTES  (128 * 128)         // 16 KB per plane
#define STAGE_BYTES (2 * TILE_BYTES)    // A | B = 32 KB
#define SMEM_BYTES  (STAGES * STAGE_BYTES)   // 96 KB -> 2 CTAs/SM

// ---------------------------------------------------------------------------
// Scratch (static device arrays: allocation-free)
// ---------------------------------------------------------------------------
static __device__ __half g_A1[(size_t)BSZ*KD1];
static __device__ __half g_Q2[(size_t)BSZ*KD1];
static __device__ __half g_H1[(size_t)BSZ*KD1];
static __device__ __half g_W1[(size_t)NMID*KD1];
static __device__ __half g_WC[(size_t)NOUT*KD2];

// ---------------------------------------------------------------------------
// PTX helpers (plain sm_80-era PTX)
// ---------------------------------------------------------------------------
__device__ __forceinline__ uint32_t smem_u32(const void* p) {
    uint32_t a;
    asm("{ .reg .u64 t; cvta.to.shared.u64 t, %1; cvt.u32.u64 %0, t; }" : "=r"(a) : "l"(p));
    return a;
}
__device__ __forceinline__ void cp16(uint32_t s, const void* g) {
    asm volatile("cp.async.cg.shared.global [%0], [%1], 16;" :: "r"(s), "l"(g));
}
__device__ __forceinline__ void cp_commit() {
    asm volatile("cp.async.commit_group;" ::: "memory");
}
__device__ __forceinline__ void cp_wait1() {
    asm volatile("cp.async.wait_group 1;" ::: "memory");
}
__device__ __forceinline__ void ldm4(uint32_t& r0, uint32_t& r1, uint32_t& r2, uint32_t& r3,
                                     uint32_t addr) {
    asm volatile("ldmatrix.sync.aligned.m8n8.x4.shared.b16 {%0,%1,%2,%3}, [%4];"
                 : "=r"(r0), "=r"(r1), "=r"(r2), "=r"(r3) : "r"(addr));
}
__device__ __forceinline__ void mma16816(float* c, const uint32_t* a, const uint32_t* b) {
    asm volatile("mma.sync.aligned.m16n8k16.row.col.f32.f16.f16.f32 "
                 "{%0,%1,%2,%3}, {%4,%5,%6,%7}, {%8,%9}, {%0,%1,%2,%3};"
                 : "+f"(c[0]), "+f"(c[1]), "+f"(c[2]), "+f"(c[3])
                 : "r"(a[0]), "r"(a[1]), "r"(a[2]), "r"(a[3]), "r"(b[0]), "r"(b[1]));
}
__device__ __forceinline__ uint32_t sw128(uint32_t o) { return o ^ ((o >> 3) & 0x70); }

__device__ __forceinline__ uint32_t h2u(float a, float b) {
    union { __half2 h; uint32_t u; } U;
    U.h = __halves2half2(__float2half_rn(a), __float2half_rn(b));
    return U.u;
}

// ---------------------------------------------------------------------------
// Merged pack kernel — fully 16B-vectorized, range-partitioned
//   NP0: A1 interleave (8 halfs/thread)          NP1: q2 (8)      NP2: w1 (8)
//   NP3: w2 even/odd dual-extract (u in [0,256)) NP4: wsk (8)
// ---------------------------------------------------------------------------
#define NP0 (BSZ * 128)
#define NP1 (BSZ * 128)
#define NP2 (NMID * KD1 / 8)
#define NP3 (NOUT * 256)          // FIXED: w2 rows have 2048 floats = 256 granules
#define NP4 (NOUT * 128)
#define NPTOT (NP0 + NP1 + NP2 + NP3 + NP4)

__global__ void pack_all(const float* __restrict__ q1, const float* __restrict__ x,
                         const float* __restrict__ q2, const float* __restrict__ w1,
                         const float* __restrict__ w2, const float* __restrict__ wsk) {
    int i = blockIdx.x * blockDim.x + threadIdx.x;
    if (i < NP0) {
        // A1[m, 8u..8u+7] = q1[m,4u+0..3] interleaved with x[m,4u+0..3]
        int m = i >> 7, u = i & 127;
        float4 a = reinterpret_cast<const float4*>(q1)[(size_t)m * 128 + u];
        float4 b = reinterpret_cast<const float4*>(x )[(size_t)m * 128 + u];
        uint4 st = make_uint4(h2u(a.x, b.x), h2u(a.y, b.y), h2u(a.z, b.z), h2u(a.w, b.w));
        *reinterpret_cast<uint4*>(&g_A1[(size_t)m * KD1 + 8 * u]) = st;
    } else if (i < NP0 + NP1) {
        int j = i - NP0;
        int m = j >> 7, u = j & 127;
        float4 v0 = reinterpret_cast<const float4*>(q2)[(size_t)m * 256 + 2 * u];
        float4 v1 = reinterpret_cast<const float4*>(q2)[(size_t)m * 256 + 2 * u + 1];
        uint4 st = make_uint4(h2u(v0.x, v0.y), h2u(v0.z, v0.w), h2u(v1.x, v1.y), h2u(v1.z, v1.w));
        *reinterpret_cast<uint4*>(&g_Q2[(size_t)m * KD1 + 8 * u]) = st;
    } else if (i < NP0 + NP1 + NP2) {
        int j = i - NP0 - NP1;
        float4 v0 = reinterpret_cast<const float4*>(w1)[(size_t)2 * j];
        float4 v1 = reinterpret_cast<const float4*>(w1)[(size_t)2 * j + 1];
        uint4 st = make_uint4(h2u(v0.x, v0.y), h2u(v0.z, v0.w), h2u(v1.x, v1.y), h2u(v1.z, v1.w));
        *reinterpret_cast<uint4*>(&g_W1[(size_t)8 * j]) = st;
    } else if (i < NP0 + NP1 + NP2 + NP3) {
        // w2 row n, float cols 8u..8u+7 (u in [0,256)):
        //   evens -> WC[n][4u..4u+3], odds -> WC[n][1024+4u..1024+4u+3]
        int j = i - NP0 - NP1 - NP2;
        int n = j >> 8, u = j & 255;
        float4 v0 = reinterpret_cast<const float4*>(w2)[(size_t)n * 512 + 2 * u];
        float4 v1 = reinterpret_cast<const float4*>(w2)[(size_t)n * 512 + 2 * u + 1];
        uint2 ev = make_uint2(h2u(v0.x, v0.z), h2u(v1.x, v1.z));
        uint2 od = make_uint2(h2u(v0.y, v0.w), h2u(v1.y, v1.w));
        *reinterpret_cast<uint2*>(&g_WC[(size_t)n * KD2 + 4 * u])        = ev;
        *reinterpret_cast<uint2*>(&g_WC[(size_t)n * KD2 + 1024 + 4 * u]) = od;
    } else if (i < NPTOT) {
        int j = i - NP0 - NP1 - NP2 - NP3;
        int n = j >> 7, u = j & 127;
        float4 v0 = reinterpret_cast<const float4*>(wsk)[(size_t)n * 256 + 2 * u];
        float4 v1 = reinterpret_cast<const float4*>(wsk)[(size_t)n * 256 + 2 * u + 1];
        uint4 st = make_uint4(h2u(v0.x, v0.y), h2u(v0.z, v0.w), h2u(v1.x, v1.y), h2u(v1.z, v1.w));
        *reinterpret_cast<uint4*>(&g_WC[(size_t)n * KD2 + 2048 + 8 * u]) = st;
    }
}

// ---------------------------------------------------------------------------
// fp16 mma.sync GEMM: 128x128 CTA, BK=64, 3-stage cp.async pipeline, 2 CTAs/SM.
// 8 warps: warp_m = wid&1 (64 rows), warp_n = wid>>1 (32 cols).
// MODE 0: A1 @ W1^T -> h1 (fp16) into g_H1
// MODE 1: [q2|h1|A1] @ WC^T -> fp32 out   (per-chunk segment pointer select)
// ---------------------------------------------------------------------------
template<int MODE>
__global__ void __launch_bounds__(256, 2) gemm_kernel(
    const float* __restrict__ pb0, const float* __restrict__ pb1,
    const float* __restrict__ psc, const float* __restrict__ pbi,
    const float* __restrict__ pmu, const float* __restrict__ pva,
    float* __restrict__ outp)
{
    extern __shared__ __align__(1024) char smem[];
    const uint32_t sb = smem_u32(smem);
    const int tid = threadIdx.x;
    const int wid = tid >> 5, lane = tid & 31;
    const int warp_m = wid & 1;      // 64-row slices
    const int warp_n = wid >> 1;     // 32-col slices
    const int blockRow = blockIdx.y * BM, blockCol = blockIdx.x * BN;

    constexpr int KC    = (MODE == 0) ? (KD1 / BK) : (KD2 / BK);   // 16 / 48
    constexpr int KDIMB = (MODE == 0) ? KD1 : KD2;                 // B row stride

    // cp.async: thread t covers row t/2 (half-row each) of both planes.
    const int ldrow = tid >> 1;
    const int ldc0  = (tid & 1) * 4;
    // A-plane row bases (all segments have row stride KD1)
    const char* pA1c = (const char*)(g_A1 + (size_t)(blockRow + ldrow) * KD1) + ldc0 * 16;
    const char* pQ2c = (const char*)(g_Q2 + (size_t)(blockRow + ldrow) * KD1) + ldc0 * 16;
    const char* pH1c = (const char*)(g_H1 + (size_t)(blockRow + ldrow) * KD1) + ldc0 * 16;
    const __half* Bg = (MODE == 0) ? g_W1 : g_WC;
    const char* pBc  = (const char*)(Bg + (size_t)(blockCol + ldrow) * KDIMB) + ldc0 * 16;

    uint32_t swoff[4];
    #pragma unroll
    for (int i = 0; i < 4; i++)
        swoff[i] = sw128((uint32_t)ldrow * 128u + (uint32_t)(ldc0 + i) * 16u);

    auto load_chunk = [&](int j) {
        const char* ga;
        if (MODE == 0) {
            ga = pA1c + (size_t)j * 128;
        } else {
            int seg = j >> 4, kc = j & 15;    // 16 chunks per 1024-col segment
            const char* base = (seg == 0) ? pQ2c : ((seg == 1) ? pH1c : pA1c);
            ga = base + (size_t)kc * 128;
        }
        const char* gb = pBc + (size_t)j * 128;
        uint32_t bs_ = sb + (uint32_t)(j % STAGES) * STAGE_BYTES;
        #pragma unroll
        for (int i = 0; i < 4; i++) cp16(bs_ +              swoff[i], ga + i * 16);
        #pragma unroll
        for (int i = 0; i < 4; i++) cp16(bs_ + TILE_BYTES + swoff[i], gb + i * 16);
    };

    float acc[4][4][4] = {};    // [mtile][ntile][frag]

    const int lrow16 = lane & 15;
    const int lhalf  = lane >> 4;

    // prologue: 2 chunks in flight
    load_chunk(0); cp_commit();
    load_chunk(1); cp_commit();

    for (int i = 0; i < KC; i++) {
        cp_wait1();            // chunk i resident
        __syncthreads();
        if (i + 2 < KC) load_chunk(i + 2);
        cp_commit();

        uint32_t st = sb + (uint32_t)(i % STAGES) * STAGE_BYTES;
        uint32_t sA = st, sB = st + TILE_BYTES;

        #pragma unroll
        for (int k16 = 0; k16 < 4; k16++) {
            const uint32_t chunk = (uint32_t)(k16 * 2 + lhalf) * 16u;
            uint32_t a[4][4], b[4][2];
            #pragma unroll
            for (int it = 0; it < 4; it++) {
                uint32_t ro = sw128((uint32_t)(warp_m * 64 + it * 16 + lrow16) * 128u + chunk);
                ldm4(a[it][0], a[it][1], a[it][2], a[it][3], sA + ro);
            }
            #pragma unroll
            for (int j2 = 0; j2 < 2; j2++) {
                uint32_t ro = sw128((uint32_t)(warp_n * 32 + j2 * 16 + lrow16) * 128u + chunk);
                uint32_t r0, r1, r2, r3;
                ldm4(r0, r1, r2, r3, sB + ro);
                b[2*j2  ][0] = r0; b[2*j2  ][1] = r2;
                b[2*j2+1][0] = r1; b[2*j2+1][1] = r3;
            }
            #pragma unroll
            for (int it = 0; it < 4; it++)
                #pragma unroll
                for (int jt = 0; jt < 4; jt++)
                    mma16816(acc[it][jt], a[it], b[jt]);
        }
    }

    // ------------------- epilogue -------------------
    __syncthreads();
    float* sp = (float*)smem;
    if (tid < BN) {
        int n = blockCol + tid;
        float se = psc[n] * rsqrtf(pva[n] + EPSBN);
        sp[tid]           = se;
        sp[BN + tid]      = pbi[n] - pmu[n] * se;
        sp[2 * BN + tid]  = (MODE == 0) ? pb0[n] : (pb0[n] + pb1[n]);
    }
    __syncthreads();

    const int groupID = lane >> 2;
    const int colPair = (lane & 3) * 2;

    #pragma unroll
    for (int it = 0; it < 4; it++) {
        #pragma unroll
        for (int jt = 0; jt < 4; jt++) {
            int lc = warp_n * 32 + jt * 8 + colPair;
            float se0 = sp[lc],      se1 = sp[lc + 1];
            float of0 = sp[BN+lc],   of1 = sp[BN+lc+1];
            float bb0 = sp[2*BN+lc], bb1 = sp[2*BN+lc+1];
            #pragma unroll
            for (int rr = 0; rr < 2; rr++) {
                int m = blockRow + warp_m * 64 + it * 16 + groupID + rr * 8;
                float v0 = fmaf(fmaxf(acc[it][jt][2*rr]   + bb0, 0.0f), se0, of0);
                float v1 = fmaf(fmaxf(acc[it][jt][2*rr+1] + bb1, 0.0f), se1, of1);
                if (MODE == 0) {
                    size_t o = (size_t)m * KD1 + blockCol + lc;
                    *reinterpret_cast<__half2*>(&g_H1[o]) =
                        __halves2half2(__float2half_rn(v0), __float2half_rn(v1));
                } else {
                    size_t o = (size_t)m * NOUT + blockCol + lc;
                    *reinterpret_cast<float2*>(&outp[o]) = make_float2(v0, v1);
                }
            }
        }
    }
}

// ---------------------------------------------------------------------------
// Launch (no static guards — identical work on every call)
// ---------------------------------------------------------------------------
extern "C" void kernel_launch(void* const* d_in, const int* in_sizes, int n_in,
                              void* d_out, int out_size) {
    const float* x    = (const float*)d_in[0];
    const float* q1   = (const float*)d_in[1];   // (2, bs, 512, 1): slice 0
    const float* q2   = (const float*)d_in[2];   // (4, bs, 1024,1): slice 0
    const float* w1   = (const float*)d_in[3];
    const float* b1   = (const float*)d_in[4];
    const float* w2   = (const float*)d_in[5];
    const float* b2   = (const float*)d_in[6];
    const float* wsk  = (const float*)d_in[7];
    const float* bsk  = (const float*)d_in[8];
    const float* s1   = (const float*)d_in[9];
    const float* bi1  = (const float*)d_in[10];
    const float* mu1  = (const float*)d_in[11];
    const float* va1  = (const float*)d_in[12];
    const float* s2   = (const float*)d_in[13];
    const float* bi2  = (const float*)d_in[14];
    const float* mu2  = (const float*)d_in[15];
    const float* va2  = (const float*)d_in[16];
    float* out = (float*)d_out;
    (void)in_sizes; (void)n_in; (void)out_size;

    cudaFuncSetAttribute(gemm_kernel<0>, cudaFuncAttributeMaxDynamicSharedMemorySize, SMEM_BYTES);
    cudaFuncSetAttribute(gemm_kernel<1>, cudaFuncAttributeMaxDynamicSharedMemorySize, SMEM_BYTES);

    pack_all<<<(NPTOT + 255) / 256, 256>>>(q1, x, q2, w1, w2, wsk);

    dim3 g1(NMID / BN, BSZ / BM);   // (8, 128)
    gemm_kernel<0><<<g1, 256, SMEM_BYTES>>>(b1, nullptr, s1, bi1, mu1, va1, nullptr);

    dim3 g2(NOUT / BN, BSZ / BM);   // (4, 128)
    gemm_kernel<1><<<g2, 256, SMEM_BYTES>>>(b2, bsk, s2, bi2, mu2, va2, out);
}